// round 13
// baseline (speedup 1.0000x reference)
#include <cuda_runtime.h>
#include <cuda.h>
#include <cuda_fp16.h>
#include <cstdint>

#define NN 10000
#define EE 160000
// log2(e)/sqrt(128) folded into Q so softmax runs in exp2 domain
#define QSCALE 0.12752532f

#define NSPLIT 15
#define CHUNK 672
#define NQT 79          // ceil(10000/128) Q tiles

// ------------- device scratch (static, zero-initialized, no allocation) -------------
__device__ float g_aggA[NN * 128];       // scatter#1 target; zeroed by conv stage 1
__device__ float g_aggB[NN * 128];       // scatter#2 target; zeroed by qkv (m==0)
__device__ float g_h[NN * 128];          // conv0 out fp32 (scatter#2 input)
__device__ __half g_h16[NN * 128];       // conv0 out fp16 (conv1 A input)
__device__ __half g_ne16[NN * 128];      // conv1 out fp16 (qkv A input)
__device__ __half g_Q[NN * 128];
__device__ __half g_K[NN * 128];
__device__ __half g_V[NN * 128];
__device__ float g_accum[128];           // zeroed by final_kernel after read
__device__ float g_pm[NQT * NSPLIT * 128];
__device__ float g_pl[NQT * NSPLIT * 128];
__device__ float g_po[(size_t)NQT * NSPLIT * 128 * 128];

// ------------- helpers -------------
__device__ __forceinline__ uint32_t cvta_s(const void* p) {
    return (uint32_t)__cvta_generic_to_shared(p);
}
__device__ __forceinline__ void ldsm_x4(uint32_t& r0, uint32_t& r1, uint32_t& r2, uint32_t& r3, uint32_t a) {
    asm volatile("ldmatrix.sync.aligned.m8n8.x4.shared.b16 {%0,%1,%2,%3}, [%4];"
                 : "=r"(r0), "=r"(r1), "=r"(r2), "=r"(r3) : "r"(a));
}
__device__ __forceinline__ void ldsm_x4_t(uint32_t& r0, uint32_t& r1, uint32_t& r2, uint32_t& r3, uint32_t a) {
    asm volatile("ldmatrix.sync.aligned.m8n8.x4.trans.shared.b16 {%0,%1,%2,%3}, [%4];"
                 : "=r"(r0), "=r"(r1), "=r"(r2), "=r"(r3) : "r"(a));
}
__device__ __forceinline__ void mma_f16(float* c, const uint32_t* a, uint32_t b0, uint32_t b1) {
    asm volatile(
        "mma.sync.aligned.m16n8k16.row.col.f32.f16.f16.f32 "
        "{%0,%1,%2,%3},{%4,%5,%6,%7},{%8,%9},{%0,%1,%2,%3};\n"
        : "+f"(c[0]), "+f"(c[1]), "+f"(c[2]), "+f"(c[3])
        : "r"(a[0]), "r"(a[1]), "r"(a[2]), "r"(a[3]), "r"(b0), "r"(b1));
}
__device__ __forceinline__ uint32_t packh2(float lo, float hi) {
    __half2 h = __floats2half2_rn(lo, hi);
    return *reinterpret_cast<uint32_t*>(&h);
}
// ---- TMA + mbarrier (attention K/V pipeline; proven R12) ----
__device__ __forceinline__ void tma2d(uint32_t dst, const CUtensorMap* map,
                                      int x, int y, uint32_t mbar) {
    asm volatile("cp.async.bulk.tensor.2d.shared::cta.global.tile.mbarrier::complete_tx::bytes "
                 "[%0], [%1, {%2, %3}], [%4];"
                 :: "r"(dst), "l"(map), "r"(x), "r"(y), "r"(mbar) : "memory");
}
__device__ __forceinline__ void mbar_init(uint32_t mbar, uint32_t count) {
    asm volatile("mbarrier.init.shared.b64 [%0], %1;" :: "r"(mbar), "r"(count) : "memory");
}
__device__ __forceinline__ void mbar_expect(uint32_t mbar, uint32_t bytes) {
    asm volatile("mbarrier.arrive.expect_tx.shared.b64 _, [%0], %1;"
                 :: "r"(mbar), "r"(bytes) : "memory");
}
__device__ __forceinline__ void mbar_wait(uint32_t mbar, uint32_t parity) {
    asm volatile(
        "{\n\t"
        ".reg .pred P1;\n\t"
        "WAIT_LOOP_%=:\n\t"
        "mbarrier.try_wait.parity.acquire.cta.shared::cta.b64 P1, [%0], %1, 0x989680;\n\t"
        "@P1 bra.uni WAIT_DONE_%=;\n\t"
        "bra.uni WAIT_LOOP_%=;\n\t"
        "WAIT_DONE_%=:\n\t"
        "}"
        :: "r"(mbar), "r"(parity) : "memory");
}

// ------------- segment_sum(x[src], dst) -------------
__global__ void scatter_kernel(const float* __restrict__ xin, const int* __restrict__ ei, int useH) {
    const float* x = useH ? g_h : xin;
    float* agg = useH ? g_aggB : g_aggA;
    long idx = (long)blockIdx.x * 256 + threadIdx.x;
    int e = (int)(idx >> 5);
    if (e >= EE) return;
    int q = ((int)idx & 31) * 4;
    int s = ei[e];
    int d = ei[EE + e];
    float4 v = *(const float4*)(x + (size_t)s * 128 + q);
    float* dp = agg + (size_t)d * 128 + q;
    asm volatile("red.global.add.v4.f32 [%0], {%1,%2,%3,%4};"
                 :: "l"(dp), "f"(v.x), "f"(v.y), "f"(v.z), "f"(v.w) : "memory");
}

// ------------- GraphConv on tensor cores, 256 thr (R10 measured version) -------------
#define CONV_SMEM (17408 * 2 + 34816 * 2)
__global__ void __launch_bounds__(256) convmma_kernel(const float* __restrict__ Xin,
                                                      const float* __restrict__ Wr,
                                                      const float* __restrict__ Wl,
                                                      const float* __restrict__ bias,
                                                      int stage) {
    extern __shared__ char smc[];
    char* Xs  = smc;
    char* As2 = smc + 17408;
    char* Wrs = smc + 34816;
    char* Wls = smc + 69632;
    __shared__ float bias_s[128];
    int tid = threadIdx.x, lane = tid & 31, w = tid >> 5;
    int rbase = blockIdx.x * 64;
    if (tid < 128) bias_s[tid] = bias[tid];

    const float* AGG = stage ? g_aggB : g_aggA;

    if (stage == 0) {
        for (int i = tid; i < 2048; i += 256) {
            int r = i >> 5, g4 = i & 31;
            int gr = rbase + r;
            float4 v = (gr < NN) ? *(const float4*)(Xin + (size_t)gr * 128 + g4 * 4)
                                 : make_float4(0.f, 0.f, 0.f, 0.f);
            uint2 u;
            u.x = packh2(v.x, v.y);
            u.y = packh2(v.z, v.w);
            *(uint2*)(Xs + r * 272 + g4 * 8) = u;
        }
    } else {
        for (int i = tid; i < 1024; i += 256) {
            int r = i >> 4, ch = i & 15;
            int gr = min(rbase + r, NN - 1);
            *(uint4*)(Xs + r * 272 + ch * 16) =
                *(const uint4*)((const char*)g_h16 + (size_t)gr * 256 + ch * 16);
        }
    }
    for (int i = tid; i < 2048; i += 256) {
        int r = i >> 5, g4 = i & 31;
        int gr = rbase + r;
        float4 v = (gr < NN) ? *(const float4*)(AGG + (size_t)gr * 128 + g4 * 4)
                             : make_float4(0.f, 0.f, 0.f, 0.f);
        uint2 u;
        u.x = packh2(v.x, v.y);
        u.y = packh2(v.z, v.w);
        *(uint2*)(As2 + r * 272 + g4 * 8) = u;
    }
    for (int i = tid; i < 4096; i += 256) {
        int k = i >> 5, g4 = i & 31;
        float4 v = *(const float4*)(Wr + (size_t)k * 128 + g4 * 4);
        uint2 u; u.x = packh2(v.x, v.y); u.y = packh2(v.z, v.w);
        *(uint2*)(Wrs + k * 272 + g4 * 8) = u;
        float4 v2 = *(const float4*)(Wl + (size_t)k * 128 + g4 * 4);
        uint2 u2; u2.x = packh2(v2.x, v2.y); u2.y = packh2(v2.z, v2.w);
        *(uint2*)(Wls + k * 272 + g4 * 8) = u2;
    }
    __syncthreads();

    int g = lane >> 3, idx = lane & 7;
    int wr_ = w & 3;
    int wc_ = w >> 2;
    float o[32];
#pragma unroll
    for (int i = 0; i < 32; i++) o[i] = 0.f;

#pragma unroll
    for (int pass = 0; pass < 2; pass++) {
        char* Abuf = pass ? As2 : Xs;
        char* Wbuf = pass ? Wls : Wrs;
#pragma unroll
        for (int kt = 0; kt < 8; kt++) {
            uint32_t a[4];
            int arow = wr_ * 16 + (g & 1) * 8 + idx;
            ldsm_x4(a[0], a[1], a[2], a[3],
                    cvta_s(Abuf + arow * 272 + kt * 32 + (g >> 1) * 16));
#pragma unroll
            for (int nt2l = 0; nt2l < 4; nt2l++) {
                int nt2 = wc_ * 4 + nt2l;
                int row = kt * 16 + (g & 1) * 8 + idx;
                uint32_t b0, b1, b2, b3;
                ldsm_x4_t(b0, b1, b2, b3,
                          cvta_s(Wbuf + row * 272 + nt2 * 32 + (g >> 1) * 16));
                mma_f16(o + (2 * nt2l) * 4, a, b0, b1);
                mma_f16(o + (2 * nt2l + 1) * 4, a, b2, b3);
            }
        }
    }

    if (stage) {
        float4 z = make_float4(0.f, 0.f, 0.f, 0.f);
        for (int i = tid; i < 2048; i += 256) {
            int r = i >> 5, g4 = i & 31;
            int gr = rbase + r;
            if (gr < NN) *(float4*)(g_aggA + (size_t)gr * 128 + g4 * 4) = z;
        }
    }

    int rr0 = wr_ * 16 + (lane >> 2), rr1 = rr0 + 8;
    int gr0 = rbase + rr0, gr1 = rbase + rr1;
#pragma unroll
    for (int nt = 0; nt < 8; nt++) {
        int c = wc_ * 64 + nt * 8 + 2 * (lane & 3);
        float v00 = o[nt * 4 + 0] + bias_s[c], v01 = o[nt * 4 + 1] + bias_s[c + 1];
        float v10 = o[nt * 4 + 2] + bias_s[c], v11 = o[nt * 4 + 3] + bias_s[c + 1];
        if (stage == 0) {
            v00 = fmaxf(v00, 0.f); v01 = fmaxf(v01, 0.f);
            v10 = fmaxf(v10, 0.f); v11 = fmaxf(v11, 0.f);
            if (gr0 < NN) {
                *(float2*)(g_h + (size_t)gr0 * 128 + c) = make_float2(v00, v01);
                *(uint32_t*)((char*)g_h16 + (size_t)gr0 * 256 + c * 2) = packh2(v00, v01);
            }
            if (gr1 < NN) {
                *(float2*)(g_h + (size_t)gr1 * 128 + c) = make_float2(v10, v11);
                *(uint32_t*)((char*)g_h16 + (size_t)gr1 * 256 + c * 2) = packh2(v10, v11);
            }
        } else {
            if (gr0 < NN)
                *(uint32_t*)((char*)g_ne16 + (size_t)gr0 * 256 + c * 2) = packh2(v00, v01);
            if (gr1 < NN)
                *(uint32_t*)((char*)g_ne16 + (size_t)gr1 * 256 + c * 2) = packh2(v10, v11);
        }
    }
}

// ------------- QKV on tensor cores (proven R8 version) -------------
#define QKV_SMEM (17408 + 34816)
__global__ void __launch_bounds__(128) qkvmma_kernel(const float* __restrict__ gi,
                                                     const float* __restrict__ WQ, const float* __restrict__ bQ,
                                                     const float* __restrict__ WQg, const float* __restrict__ bQg,
                                                     const float* __restrict__ WK, const float* __restrict__ bK,
                                                     const float* __restrict__ WKg, const float* __restrict__ bKg,
                                                     const float* __restrict__ WV, const float* __restrict__ bV,
                                                     const float* __restrict__ WVg, const float* __restrict__ bVg) {
    extern __shared__ char smq[];
    char* Ns = smq;
    char* Ws = smq + 17408;
    __shared__ float cb_s[128];
    int m = blockIdx.y;
    const float* W  = m == 0 ? WQ  : (m == 1 ? WK  : WV);
    const float* b  = m == 0 ? bQ  : (m == 1 ? bK  : bV);
    const float* bg = m == 0 ? bQg : (m == 1 ? bKg : bVg);
    const float* Wg = m == 0 ? WQg : (m == 1 ? WKg : WVg);
    __half* out = m == 0 ? g_Q : (m == 1 ? g_K : g_V);
    float scale = m == 0 ? QSCALE : 1.0f;
    int tid = threadIdx.x, lane = tid & 31, w = tid >> 5;
    int rbase = blockIdx.x * 64;

    {
        float s = b[tid] + bg[tid];
        for (int i = 0; i < 64; i++) s += gi[i] * Wg[i * 128 + tid];
        cb_s[tid] = s;
    }
    for (int i = tid; i < 1024; i += 128) {
        int r = i >> 4, ch = i & 15;
        int gr = min(rbase + r, NN - 1);
        *(uint4*)(Ns + r * 272 + ch * 16) =
            *(const uint4*)((const char*)g_ne16 + (size_t)gr * 256 + ch * 16);
    }
    for (int i = tid; i < 4096; i += 128) {
        int k = i >> 5, g4 = i & 31;
        float4 v = *(const float4*)(W + (size_t)k * 128 + g4 * 4);
        uint2 u; u.x = packh2(v.x, v.y); u.y = packh2(v.z, v.w);
        *(uint2*)(Ws + k * 272 + g4 * 8) = u;
    }
    __syncthreads();

    int g = lane >> 3, idx = lane & 7;
    float o[64];
#pragma unroll
    for (int i = 0; i < 64; i++) o[i] = 0.f;

#pragma unroll
    for (int kt = 0; kt < 8; kt++) {
        uint32_t a[4];
        int arow = w * 16 + (g & 1) * 8 + idx;
        ldsm_x4(a[0], a[1], a[2], a[3],
                cvta_s(Ns + arow * 272 + kt * 32 + (g >> 1) * 16));
#pragma unroll
        for (int nt2 = 0; nt2 < 8; nt2++) {
            int row = kt * 16 + (g & 1) * 8 + idx;
            uint32_t b0, b1, b2, b3;
            ldsm_x4_t(b0, b1, b2, b3,
                      cvta_s(Ws + row * 272 + nt2 * 32 + (g >> 1) * 16));
            mma_f16(o + (2 * nt2) * 4, a, b0, b1);
            mma_f16(o + (2 * nt2 + 1) * 4, a, b2, b3);
        }
    }

    if (m == 0) {
        float4 z = make_float4(0.f, 0.f, 0.f, 0.f);
        for (int i = tid; i < 2048; i += 128) {
            int r = i >> 5, g4 = i & 31;
            int gr = rbase + r;
            if (gr < NN) *(float4*)(g_aggB + (size_t)gr * 128 + g4 * 4) = z;
        }
    }

    int rr0 = w * 16 + (lane >> 2), rr1 = rr0 + 8;
    int gr0 = rbase + rr0, gr1 = rbase + rr1;
#pragma unroll
    for (int nt = 0; nt < 16; nt++) {
        int c = nt * 8 + 2 * (lane & 3);
        float v00 = (o[nt * 4 + 0] + cb_s[c]) * scale, v01 = (o[nt * 4 + 1] + cb_s[c + 1]) * scale;
        float v10 = (o[nt * 4 + 2] + cb_s[c]) * scale, v11 = (o[nt * 4 + 3] + cb_s[c + 1]) * scale;
        if (gr0 < NN) *(uint32_t*)((char*)out + (size_t)gr0 * 256 + c * 2) = packh2(v00, v01);
        if (gr1 < NN) *(uint32_t*)((char*)out + (size_t)gr1 * 256 + c * 2) = packh2(v10, v11);
    }
}

// ------------- split-KV flash attention: Br=128, Bc=64, TMA (SW128), 2 CTAs/SM -------------
// smem: Q [0, 34816) padded 272B rows | mbars [34816, 34832) | stages at 35840
// stage (32KB): Kbox0 8KB | Kbox1 8KB | Vbox0 8KB | Vbox1 8KB  (boxes are [64 elem, 64 rows])
#define KSTR 272
#define SM_MBAR 34816
#define SM_ST 35840
#define KV_STAGE 32768
#define SMEM_TOTAL (SM_ST + 2 * KV_STAGE)   // 101376 -> 2 CTAs/SM

__global__ void __launch_bounds__(256, 2) attn_kernel(const __grid_constant__ CUtensorMap tmK,
                                                      const __grid_constant__ CUtensorMap tmV) {
    extern __shared__ char sm[];
    __half* Qs = (__half*)sm;
    int tid = threadIdx.x, lane = tid & 31, w = tid >> 5;
    int unit = blockIdx.x;
    int qtile = unit / NSPLIT, split = unit - qtile * NSPLIT;
    int rbase = qtile * 128;
    int kv0 = split * CHUNK;
    int kv1 = min(kv0 + CHUNK, NN);
    int niter = (kv1 - kv0 + 63) >> 6;   // 10..11

    uint32_t smem_u32 = cvta_s(sm);
    uint32_t mb0 = smem_u32 + SM_MBAR;
    uint32_t mb1 = smem_u32 + SM_MBAR + 8;

    if (tid == 0) {
        mbar_init(mb0, 1);
        mbar_init(mb1, 1);
    }
    // Q tile: plain loads into padded 272B-row layout (one-time)
    for (int i = tid; i < 128 * 16; i += 256) {
        int r = i >> 4, ch = i & 15;
        int gr = min(rbase + r, NN - 1);
        *(uint4*)((char*)Qs + r * KSTR + ch * 16) =
            *(const uint4*)((const char*)g_Q + (size_t)gr * 256 + ch * 16);
    }
    __syncthreads();   // mbar init + Q visible

    // issue stage 0 and stage 1 K/V TMA loads (4 box ops each; OOB rows auto-zero)
    if (tid == 0) {
        mbar_expect(mb0, KV_STAGE);
        uint32_t st0 = smem_u32 + SM_ST;
        tma2d(st0 +     0, &tmK,  0, kv0, mb0);
        tma2d(st0 +  8192, &tmK, 64, kv0, mb0);
        tma2d(st0 + 16384, &tmV,  0, kv0, mb0);
        tma2d(st0 + 24576, &tmV, 64, kv0, mb0);
        mbar_expect(mb1, KV_STAGE);
        uint32_t st1 = smem_u32 + SM_ST + KV_STAGE;
        tma2d(st1 +     0, &tmK,  0, kv0 + 64, mb1);
        tma2d(st1 +  8192, &tmK, 64, kv0 + 64, mb1);
        tma2d(st1 + 16384, &tmV,  0, kv0 + 64, mb1);
        tma2d(st1 + 24576, &tmV, 64, kv0 + 64, mb1);
    }

    float M0 = -1e30f, M1 = -1e30f, l0 = 0.f, l1 = 0.f;
    float o[64];
#pragma unroll
    for (int i = 0; i < 64; i++) o[i] = 0.f;

    int g = lane >> 3, idx = lane & 7;

    for (int it = 0; it < niter; it++) {
        int jb = kv0 + it * 64;
        int st = it & 1;
        uint32_t stb = smem_u32 + SM_ST + st * KV_STAGE;
        uint32_t Kb = stb;             // 2 K boxes (8KB each)
        uint32_t Vb = stb + 16384;     // 2 V boxes
        uint32_t mb = st ? mb1 : mb0;

        mbar_wait(mb, (it >> 1) & 1);

        float s[32];
#pragma unroll
        for (int i = 0; i < 32; i++) s[i] = 0.f;

        // S = Q @ K^T   (qa reloaded per kt to cap registers; Bc=64 -> nt2 0..3)
#pragma unroll
        for (int kt = 0; kt < 8; kt++) {
            uint32_t qa[4];
            int qrow = w * 16 + (g & 1) * 8 + idx;
            ldsm_x4(qa[0], qa[1], qa[2], qa[3],
                    cvta_s((char*)Qs + qrow * KSTR + kt * 32 + (g >> 1) * 16));
#pragma unroll
            for (int nt2 = 0; nt2 < 4; nt2++) {
                int row = nt2 * 16 + (g & 2) * 4 + idx;
                int chunk = ((kt * 2 + (g & 1)) & 7) ^ (row & 7);
                uint32_t a = Kb + (kt >> 2) * 8192 + row * 128 + (chunk << 4);
                uint32_t b0, b1, b2, b3;
                ldsm_x4(b0, b1, b2, b3, a);
                mma_f16(s + (2 * nt2) * 4, qa, b0, b1);
                mma_f16(s + (2 * nt2 + 1) * 4, qa, b2, b3);
            }
        }

        // mask tail keys
        if (jb + 64 > kv1) {
#pragma unroll
            for (int nt = 0; nt < 8; nt++) {
                int j0 = jb + nt * 8 + 2 * (lane & 3);
                if (j0 >= kv1) { s[nt * 4 + 0] = -1e30f; s[nt * 4 + 2] = -1e30f; }
                if (j0 + 1 >= kv1) { s[nt * 4 + 1] = -1e30f; s[nt * 4 + 3] = -1e30f; }
            }
        }

        // online softmax (exp2 domain)
        float m0 = -1e30f, m1 = -1e30f;
#pragma unroll
        for (int nt = 0; nt < 8; nt++) {
            m0 = fmaxf(m0, fmaxf(s[nt * 4 + 0], s[nt * 4 + 1]));
            m1 = fmaxf(m1, fmaxf(s[nt * 4 + 2], s[nt * 4 + 3]));
        }
        m0 = fmaxf(m0, __shfl_xor_sync(0xffffffffu, m0, 1));
        m0 = fmaxf(m0, __shfl_xor_sync(0xffffffffu, m0, 2));
        m1 = fmaxf(m1, __shfl_xor_sync(0xffffffffu, m1, 1));
        m1 = fmaxf(m1, __shfl_xor_sync(0xffffffffu, m1, 2));
        float Mn0 = fmaxf(M0, m0), Mn1 = fmaxf(M1, m1);
        float sc0 = exp2f(M0 - Mn0), sc1 = exp2f(M1 - Mn1);
        M0 = Mn0; M1 = Mn1;
        float r0 = 0.f, r1 = 0.f;
#pragma unroll
        for (int nt = 0; nt < 8; nt++) {
            s[nt * 4 + 0] = exp2f(s[nt * 4 + 0] - M0);
            s[nt * 4 + 1] = exp2f(s[nt * 4 + 1] - M0);
            s[nt * 4 + 2] = exp2f(s[nt * 4 + 2] - M1);
            s[nt * 4 + 3] = exp2f(s[nt * 4 + 3] - M1);
            r0 += s[nt * 4 + 0] + s[nt * 4 + 1];
            r1 += s[nt * 4 + 2] + s[nt * 4 + 3];
        }
        r0 += __shfl_xor_sync(0xffffffffu, r0, 1);
        r0 += __shfl_xor_sync(0xffffffffu, r0, 2);
        r1 += __shfl_xor_sync(0xffffffffu, r1, 1);
        r1 += __shfl_xor_sync(0xffffffffu, r1, 2);
        l0 = l0 * sc0 + r0;
        l1 = l1 * sc1 + r1;
#pragma unroll
        for (int nt = 0; nt < 16; nt++) {
            o[nt * 4 + 0] *= sc0; o[nt * 4 + 1] *= sc0;
            o[nt * 4 + 2] *= sc1; o[nt * 4 + 3] *= sc1;
        }

        // O += P @ V   (kt 0..3 key-chunks, nt2 0..7 output cols)
#pragma unroll
        for (int kt = 0; kt < 4; kt++) {
            uint32_t pa[4];
            pa[0] = packh2(s[8 * kt + 0], s[8 * kt + 1]);
            pa[1] = packh2(s[8 * kt + 2], s[8 * kt + 3]);
            pa[2] = packh2(s[8 * kt + 4], s[8 * kt + 5]);
            pa[3] = packh2(s[8 * kt + 6], s[8 * kt + 7]);
#pragma unroll
            for (int nt2 = 0; nt2 < 8; nt2++) {
                int row = kt * 16 + (g & 1) * 8 + idx;
                int chunk = ((nt2 * 2 + (g >> 1)) & 7) ^ (row & 7);
                uint32_t a = Vb + (nt2 >> 2) * 8192 + row * 128 + (chunk << 4);
                uint32_t b0, b1, b2, b3;
                ldsm_x4_t(b0, b1, b2, b3, a);
                mma_f16(o + (2 * nt2) * 4, pa, b0, b1);
                mma_f16(o + (2 * nt2 + 1) * 4, pa, b2, b3);
            }
        }
        __syncthreads();   // all warps done reading stage st

        // refill this stage for iteration it+2
        if (it + 2 < niter && tid == 0) {
            int jn = kv0 + (it + 2) * 64;
            mbar_expect(mb, KV_STAGE);
            tma2d(stb +     0, &tmK,  0, jn, mb);
            tma2d(stb +  8192, &tmK, 64, jn, mb);
            tma2d(stb + 16384, &tmV,  0, jn, mb);
            tma2d(stb + 24576, &tmV, 64, jn, mb);
        }
    }

    // write partials (unnormalized o, plus m, l)
    int rr0 = w * 16 + (lane >> 2);
    int rr1 = rr0 + 8;
    size_t ubase = (size_t)unit * 128;
    if ((lane & 3) == 0) {
        g_pm[ubase + rr0] = M0;
        g_pl[ubase + rr0] = l0;
        g_pm[ubase + rr1] = M1;
        g_pl[ubase + rr1] = l1;
    }
#pragma unroll
    for (int nt = 0; nt < 16; nt++) {
        int c = nt * 8 + 2 * (lane & 3);
        *(float2*)&g_po[(ubase + rr0) * 128 + c] = make_float2(o[nt * 4 + 0], o[nt * 4 + 1]);
        *(float2*)&g_po[(ubase + rr1) * 128 + c] = make_float2(o[nt * 4 + 2], o[nt * 4 + 3]);
    }
}

// ------------- merge splits + column mean-sum -------------
__global__ void __launch_bounds__(128) merge_kernel() {
    int c = threadIdx.x;
    int rstart = blockIdx.x * 16;
    float acc = 0.f;
    for (int i = 0; i < 16; i++) {
        int r = rstart + i;
        if (r >= NN) break;
        int tile = r >> 7, row = r & 127;
        int base = tile * (NSPLIT * 128) + row;
        float M = -1e30f;
#pragma unroll
        for (int s = 0; s < NSPLIT; s++) M = fmaxf(M, g_pm[base + s * 128]);
        float L = 0.f, oc = 0.f;
#pragma unroll
        for (int s = 0; s < NSPLIT; s++) {
            float sc = exp2f(g_pm[base + s * 128] - M);
            L += g_pl[base + s * 128] * sc;
            oc += g_po[(size_t)(base + s * 128) * 128 + c] * sc;
        }
        acc += oc / L;
    }
    atomicAdd(&g_accum[c], acc);
}

// ------------- mean -> Wo -> MLP -> softmax; re-zeros g_accum -------------
__global__ void __launch_bounds__(128) final_kernel(const float* Wo, const float* bo,
                                                    const float* W1, const float* b1v,
                                                    const float* W2, const float* b2v,
                                                    const float* W3, const float* b3v,
                                                    float* out) {
    __shared__ float v0[128], v1[128], v2[64], v3[32], red[2];
    int t = threadIdx.x;
    v0[t] = g_accum[t] * (1.0f / NN);
    g_accum[t] = 0.f;   // replay invariant
    __syncthreads();
    float s = bo[t];
    for (int i = 0; i < 128; i++) s += v0[i] * Wo[i * 128 + t];
    v1[t] = s;
    __syncthreads();
    if (t < 64) {
        float s2 = b1v[t];
        for (int i = 0; i < 128; i++) s2 += v1[i] * W1[i * 64 + t];
        v2[t] = fmaxf(s2, 0.f);
    }
    __syncthreads();
    if (t < 32) {
        float s3 = b2v[t];
        for (int i = 0; i < 64; i++) s3 += v2[i] * W2[i * 32 + t];
        v3[t] = fmaxf(s3, 0.f);
    }
    __syncthreads();
    float lg = b3v[t];
    for (int i = 0; i < 32; i++) lg += v3[i] * W3[i * 128 + t];
    v1[t] = lg;
    __syncthreads();
    if (t == 0) {
        float mx = -1e30f;
        for (int i = 0; i < 128; i++) mx = fmaxf(mx, v1[i]);
        float sm = 0.f;
        for (int i = 0; i < 128; i++) sm += expf(v1[i] - mx);
        red[0] = mx; red[1] = sm;
    }
    __syncthreads();
    out[t] = expf(lg - red[0]) / red[1];
}

// ------------- launch -------------
extern "C" void kernel_launch(void* const* d_in, const int* in_sizes, int n_in,
                              void* d_out, int out_size) {
    const float* nf = (const float*)d_in[0];
    const float* gi = (const float*)d_in[1];
    const int* ei = (const int*)d_in[2];
    const float* W1_root = (const float*)d_in[3];
    const float* W1_rel = (const float*)d_in[4];
    const float* b1 = (const float*)d_in[5];
    const float* W2_root = (const float*)d_in[6];
    const float* W2_rel = (const float*)d_in[7];
    const float* b2 = (const float*)d_in[8];
    const float* WQ = (const float*)d_in[9];
    const float* bQ = (const float*)d_in[10];
    const float* WK = (const float*)d_in[11];
    const float* bK = (const float*)d_in[12];
    const float* WV = (const float*)d_in[13];
    const float* bV = (const float*)d_in[14];
    const float* WQg = (const float*)d_in[15];
    const float* bQg = (const float*)d_in[16];
    const float* WKg = (const float*)d_in[17];
    const float* bKg = (const float*)d_in[18];
    const float* WVg = (const float*)d_in[19];
    const float* bVg = (const float*)d_in[20];
    const float* Wo = (const float*)d_in[21];
    const float* bo = (const float*)d_in[22];
    const float* Wfc1 = (const float*)d_in[23];
    const float* bfc1 = (const float*)d_in[24];
    const float* Wfc2 = (const float*)d_in[25];
    const float* bfc2 = (const float*)d_in[26];
    const float* Wfc3 = (const float*)d_in[27];
    const float* bfc3 = (const float*)d_in[28];

    static int attr_set = 0;
    static CUtensorMap h_tmK, h_tmV;
    if (!attr_set) {
        cudaFuncSetAttribute(attn_kernel, cudaFuncAttributeMaxDynamicSharedMemorySize, SMEM_TOTAL);
        cudaFuncSetAttribute(convmma_kernel, cudaFuncAttributeMaxDynamicSharedMemorySize, CONV_SMEM);
        cudaFuncSetAttribute(qkvmma_kernel, cudaFuncAttributeMaxDynamicSharedMemorySize, QKV_SMEM);

        typedef CUresult (*PFN_encode)(CUtensorMap*, CUtensorMapDataType, cuuint32_t, void*,
                                       const cuuint64_t*, const cuuint64_t*,
                                       const cuuint32_t*, const cuuint32_t*,
                                       CUtensorMapInterleave, CUtensorMapSwizzle,
                                       CUtensorMapL2promotion, CUtensorMapFloatOOBfill);
        PFN_encode encode = nullptr;
        cudaDriverEntryPointQueryResult qr;
        cudaGetDriverEntryPoint("cuTensorMapEncodeTiled", (void**)&encode,
                                cudaEnableDefault, &qr);
        void *pK = nullptr, *pV = nullptr;
        cudaGetSymbolAddress(&pK, g_K);
        cudaGetSymbolAddress(&pV, g_V);
        cuuint64_t dims[2] = {128, NN};
        cuuint64_t strides[1] = {256};            // bytes between rows
        cuuint32_t box[2] = {64, 64};             // 64 fp16 = 128B (SW128 limit), 64 rows
        cuuint32_t estr[2] = {1, 1};
        encode(&h_tmK, CU_TENSOR_MAP_DATA_TYPE_FLOAT16, 2, pK, dims, strides, box, estr,
               CU_TENSOR_MAP_INTERLEAVE_NONE, CU_TENSOR_MAP_SWIZZLE_128B,
               CU_TENSOR_MAP_L2_PROMOTION_L2_128B, CU_TENSOR_MAP_FLOAT_OOB_FILL_NONE);
        encode(&h_tmV, CU_TENSOR_MAP_DATA_TYPE_FLOAT16, 2, pV, dims, strides, box, estr,
               CU_TENSOR_MAP_INTERLEAVE_NONE, CU_TENSOR_MAP_SWIZZLE_128B,
               CU_TENSOR_MAP_L2_PROMOTION_L2_128B, CU_TENSOR_MAP_FLOAT_OOB_FILL_NONE);
        attr_set = 1;
    }

    scatter_kernel<<<20000, 256>>>(nf, ei, 0);                                   // 0 -> aggA
    convmma_kernel<<<157, 256, CONV_SMEM>>>(nf, W1_root, W1_rel, b1, 0);         // 1 reads aggA
    scatter_kernel<<<20000, 256>>>(nf, ei, 1);                                   // 2 -> aggB
    convmma_kernel<<<157, 256, CONV_SMEM>>>(nf, W2_root, W2_rel, b2, 1);         // 3 reads aggB, zeros aggA  <- ncu slot
    qkvmma_kernel<<<dim3(157, 3), 128, QKV_SMEM>>>(gi, WQ, bQ, WQg, bQg,
                                                   WK, bK, WKg, bKg,
                                                   WV, bV, WVg, bVg);            // 4 zeros aggB (m==0)
    attn_kernel<<<NQT * NSPLIT, 256, SMEM_TOTAL>>>(h_tmK, h_tmV);                // 5
    merge_kernel<<<625, 128>>>();                                                // 6
    final_kernel<<<1, 128>>>(Wo, bo, Wfc1, bfc1, Wfc2, bfc2, Wfc3, bfc3, (float*)d_out);  // 7
}

// round 14
// speedup vs baseline: 1.2093x; 1.2093x over previous
#include <cuda_runtime.h>
#include <cuda.h>
#include <cuda_fp16.h>
#include <cstdint>

#define NN 10000
#define EE 160000
// log2(e)/sqrt(128) folded into Q so softmax runs in exp2 domain
#define QSCALE 0.12752532f

#define NSPLIT 9
#define CHUNK 1112
#define NQT 79          // ceil(10000/128) Q tiles

// ------------- device scratch (static, zero-initialized, no allocation) -------------
__device__ float g_aggA[NN * 128];       // scatter#1 target; zeroed by conv stage 1
__device__ float g_aggB[NN * 128];       // scatter#2 target; zeroed by qkv (m==0)
__device__ float g_h[NN * 128];          // conv0 out fp32 (scatter#2 input)
__device__ __half g_h16[NN * 128];       // conv0 out fp16 (conv1 A input)
__device__ __half g_ne16[NN * 128];      // conv1 out fp16 (qkv A input)
__device__ __half g_Q[NN * 128];
__device__ __half g_K[NN * 128];
__device__ __half g_V[NN * 128];
__device__ float g_accum[128];           // zeroed by final_kernel after read
__device__ float g_pm[NQT * NSPLIT * 128];
__device__ float g_pl[NQT * NSPLIT * 128];
__device__ float g_po[(size_t)NQT * NSPLIT * 128 * 128];

// ------------- helpers -------------
__device__ __forceinline__ uint32_t cvta_s(const void* p) {
    return (uint32_t)__cvta_generic_to_shared(p);
}
__device__ __forceinline__ void ldsm_x4(uint32_t& r0, uint32_t& r1, uint32_t& r2, uint32_t& r3, uint32_t a) {
    asm volatile("ldmatrix.sync.aligned.m8n8.x4.shared.b16 {%0,%1,%2,%3}, [%4];"
                 : "=r"(r0), "=r"(r1), "=r"(r2), "=r"(r3) : "r"(a));
}
__device__ __forceinline__ void ldsm_x4_t(uint32_t& r0, uint32_t& r1, uint32_t& r2, uint32_t& r3, uint32_t a) {
    asm volatile("ldmatrix.sync.aligned.m8n8.x4.trans.shared.b16 {%0,%1,%2,%3}, [%4];"
                 : "=r"(r0), "=r"(r1), "=r"(r2), "=r"(r3) : "r"(a));
}
__device__ __forceinline__ void mma_f16(float* c, const uint32_t* a, uint32_t b0, uint32_t b1) {
    asm volatile(
        "mma.sync.aligned.m16n8k16.row.col.f32.f16.f16.f32 "
        "{%0,%1,%2,%3},{%4,%5,%6,%7},{%8,%9},{%0,%1,%2,%3};\n"
        : "+f"(c[0]), "+f"(c[1]), "+f"(c[2]), "+f"(c[3])
        : "r"(a[0]), "r"(a[1]), "r"(a[2]), "r"(a[3]), "r"(b0), "r"(b1));
}
__device__ __forceinline__ uint32_t packh2(float lo, float hi) {
    __half2 h = __floats2half2_rn(lo, hi);
    return *reinterpret_cast<uint32_t*>(&h);
}
// ---- TMA + mbarrier (attention K/V pipeline; proven R12) ----
__device__ __forceinline__ void tma2d(uint32_t dst, const CUtensorMap* map,
                                      int x, int y, uint32_t mbar) {
    asm volatile("cp.async.bulk.tensor.2d.shared::cta.global.tile.mbarrier::complete_tx::bytes "
                 "[%0], [%1, {%2, %3}], [%4];"
                 :: "r"(dst), "l"(map), "r"(x), "r"(y), "r"(mbar) : "memory");
}
__device__ __forceinline__ void mbar_init(uint32_t mbar, uint32_t count) {
    asm volatile("mbarrier.init.shared.b64 [%0], %1;" :: "r"(mbar), "r"(count) : "memory");
}
__device__ __forceinline__ void mbar_expect(uint32_t mbar, uint32_t bytes) {
    asm volatile("mbarrier.arrive.expect_tx.shared.b64 _, [%0], %1;"
                 :: "r"(mbar), "r"(bytes) : "memory");
}
__device__ __forceinline__ void mbar_wait(uint32_t mbar, uint32_t parity) {
    asm volatile(
        "{\n\t"
        ".reg .pred P1;\n\t"
        "WAIT_LOOP_%=:\n\t"
        "mbarrier.try_wait.parity.acquire.cta.shared::cta.b64 P1, [%0], %1, 0x989680;\n\t"
        "@P1 bra.uni WAIT_DONE_%=;\n\t"
        "bra.uni WAIT_LOOP_%=;\n\t"
        "WAIT_DONE_%=:\n\t"
        "}"
        :: "r"(mbar), "r"(parity) : "memory");
}

// ------------- segment_sum(x[src], dst) -------------
__global__ void scatter_kernel(const float* __restrict__ xin, const int* __restrict__ ei, int useH) {
    const float* x = useH ? g_h : xin;
    float* agg = useH ? g_aggB : g_aggA;
    long idx = (long)blockIdx.x * 256 + threadIdx.x;
    int e = (int)(idx >> 5);
    if (e >= EE) return;
    int q = ((int)idx & 31) * 4;
    int s = ei[e];
    int d = ei[EE + e];
    float4 v = *(const float4*)(x + (size_t)s * 128 + q);
    float* dp = agg + (size_t)d * 128 + q;
    asm volatile("red.global.add.v4.f32 [%0], {%1,%2,%3,%4};"
                 :: "l"(dp), "f"(v.x), "f"(v.y), "f"(v.z), "f"(v.w) : "memory");
}

// ------------- GraphConv on tensor cores, 256 thr (R10 measured version) -------------
#define CONV_SMEM (17408 * 2 + 34816 * 2)
__global__ void __launch_bounds__(256) convmma_kernel(const float* __restrict__ Xin,
                                                      const float* __restrict__ Wr,
                                                      const float* __restrict__ Wl,
                                                      const float* __restrict__ bias,
                                                      int stage) {
    extern __shared__ char smc[];
    char* Xs  = smc;
    char* As2 = smc + 17408;
    char* Wrs = smc + 34816;
    char* Wls = smc + 69632;
    __shared__ float bias_s[128];
    int tid = threadIdx.x, lane = tid & 31, w = tid >> 5;
    int rbase = blockIdx.x * 64;
    if (tid < 128) bias_s[tid] = bias[tid];

    const float* AGG = stage ? g_aggB : g_aggA;

    if (stage == 0) {
        for (int i = tid; i < 2048; i += 256) {
            int r = i >> 5, g4 = i & 31;
            int gr = rbase + r;
            float4 v = (gr < NN) ? *(const float4*)(Xin + (size_t)gr * 128 + g4 * 4)
                                 : make_float4(0.f, 0.f, 0.f, 0.f);
            uint2 u;
            u.x = packh2(v.x, v.y);
            u.y = packh2(v.z, v.w);
            *(uint2*)(Xs + r * 272 + g4 * 8) = u;
        }
    } else {
        for (int i = tid; i < 1024; i += 256) {
            int r = i >> 4, ch = i & 15;
            int gr = min(rbase + r, NN - 1);
            *(uint4*)(Xs + r * 272 + ch * 16) =
                *(const uint4*)((const char*)g_h16 + (size_t)gr * 256 + ch * 16);
        }
    }
    for (int i = tid; i < 2048; i += 256) {
        int r = i >> 5, g4 = i & 31;
        int gr = rbase + r;
        float4 v = (gr < NN) ? *(const float4*)(AGG + (size_t)gr * 128 + g4 * 4)
                             : make_float4(0.f, 0.f, 0.f, 0.f);
        uint2 u;
        u.x = packh2(v.x, v.y);
        u.y = packh2(v.z, v.w);
        *(uint2*)(As2 + r * 272 + g4 * 8) = u;
    }
    for (int i = tid; i < 4096; i += 256) {
        int k = i >> 5, g4 = i & 31;
        float4 v = *(const float4*)(Wr + (size_t)k * 128 + g4 * 4);
        uint2 u; u.x = packh2(v.x, v.y); u.y = packh2(v.z, v.w);
        *(uint2*)(Wrs + k * 272 + g4 * 8) = u;
        float4 v2 = *(const float4*)(Wl + (size_t)k * 128 + g4 * 4);
        uint2 u2; u2.x = packh2(v2.x, v2.y); u2.y = packh2(v2.z, v2.w);
        *(uint2*)(Wls + k * 272 + g4 * 8) = u2;
    }
    __syncthreads();

    int g = lane >> 3, idx = lane & 7;
    int wr_ = w & 3;
    int wc_ = w >> 2;
    float o[32];
#pragma unroll
    for (int i = 0; i < 32; i++) o[i] = 0.f;

#pragma unroll
    for (int pass = 0; pass < 2; pass++) {
        char* Abuf = pass ? As2 : Xs;
        char* Wbuf = pass ? Wls : Wrs;
#pragma unroll
        for (int kt = 0; kt < 8; kt++) {
            uint32_t a[4];
            int arow = wr_ * 16 + (g & 1) * 8 + idx;
            ldsm_x4(a[0], a[1], a[2], a[3],
                    cvta_s(Abuf + arow * 272 + kt * 32 + (g >> 1) * 16));
#pragma unroll
            for (int nt2l = 0; nt2l < 4; nt2l++) {
                int nt2 = wc_ * 4 + nt2l;
                int row = kt * 16 + (g & 1) * 8 + idx;
                uint32_t b0, b1, b2, b3;
                ldsm_x4_t(b0, b1, b2, b3,
                          cvta_s(Wbuf + row * 272 + nt2 * 32 + (g >> 1) * 16));
                mma_f16(o + (2 * nt2l) * 4, a, b0, b1);
                mma_f16(o + (2 * nt2l + 1) * 4, a, b2, b3);
            }
        }
    }

    if (stage) {
        float4 z = make_float4(0.f, 0.f, 0.f, 0.f);
        for (int i = tid; i < 2048; i += 256) {
            int r = i >> 5, g4 = i & 31;
            int gr = rbase + r;
            if (gr < NN) *(float4*)(g_aggA + (size_t)gr * 128 + g4 * 4) = z;
        }
    }

    int rr0 = wr_ * 16 + (lane >> 2), rr1 = rr0 + 8;
    int gr0 = rbase + rr0, gr1 = rbase + rr1;
#pragma unroll
    for (int nt = 0; nt < 8; nt++) {
        int c = wc_ * 64 + nt * 8 + 2 * (lane & 3);
        float v00 = o[nt * 4 + 0] + bias_s[c], v01 = o[nt * 4 + 1] + bias_s[c + 1];
        float v10 = o[nt * 4 + 2] + bias_s[c], v11 = o[nt * 4 + 3] + bias_s[c + 1];
        if (stage == 0) {
            v00 = fmaxf(v00, 0.f); v01 = fmaxf(v01, 0.f);
            v10 = fmaxf(v10, 0.f); v11 = fmaxf(v11, 0.f);
            if (gr0 < NN) {
                *(float2*)(g_h + (size_t)gr0 * 128 + c) = make_float2(v00, v01);
                *(uint32_t*)((char*)g_h16 + (size_t)gr0 * 256 + c * 2) = packh2(v00, v01);
            }
            if (gr1 < NN) {
                *(float2*)(g_h + (size_t)gr1 * 128 + c) = make_float2(v10, v11);
                *(uint32_t*)((char*)g_h16 + (size_t)gr1 * 256 + c * 2) = packh2(v10, v11);
            }
        } else {
            if (gr0 < NN)
                *(uint32_t*)((char*)g_ne16 + (size_t)gr0 * 256 + c * 2) = packh2(v00, v01);
            if (gr1 < NN)
                *(uint32_t*)((char*)g_ne16 + (size_t)gr1 * 256 + c * 2) = packh2(v10, v11);
        }
    }
}

// ------------- QKV on tensor cores (proven R8 version) -------------
#define QKV_SMEM (17408 + 34816)
__global__ void __launch_bounds__(128) qkvmma_kernel(const float* __restrict__ gi,
                                                     const float* __restrict__ WQ, const float* __restrict__ bQ,
                                                     const float* __restrict__ WQg, const float* __restrict__ bQg,
                                                     const float* __restrict__ WK, const float* __restrict__ bK,
                                                     const float* __restrict__ WKg, const float* __restrict__ bKg,
                                                     const float* __restrict__ WV, const float* __restrict__ bV,
                                                     const float* __restrict__ WVg, const float* __restrict__ bVg) {
    extern __shared__ char smq[];
    char* Ns = smq;
    char* Ws = smq + 17408;
    __shared__ float cb_s[128];
    int m = blockIdx.y;
    const float* W  = m == 0 ? WQ  : (m == 1 ? WK  : WV);
    const float* b  = m == 0 ? bQ  : (m == 1 ? bK  : bV);
    const float* bg = m == 0 ? bQg : (m == 1 ? bKg : bVg);
    const float* Wg = m == 0 ? WQg : (m == 1 ? WKg : WVg);
    __half* out = m == 0 ? g_Q : (m == 1 ? g_K : g_V);
    float scale = m == 0 ? QSCALE : 1.0f;
    int tid = threadIdx.x, lane = tid & 31, w = tid >> 5;
    int rbase = blockIdx.x * 64;

    {
        float s = b[tid] + bg[tid];
        for (int i = 0; i < 64; i++) s += gi[i] * Wg[i * 128 + tid];
        cb_s[tid] = s;
    }
    for (int i = tid; i < 1024; i += 128) {
        int r = i >> 4, ch = i & 15;
        int gr = min(rbase + r, NN - 1);
        *(uint4*)(Ns + r * 272 + ch * 16) =
            *(const uint4*)((const char*)g_ne16 + (size_t)gr * 256 + ch * 16);
    }
    for (int i = tid; i < 4096; i += 128) {
        int k = i >> 5, g4 = i & 31;
        float4 v = *(const float4*)(W + (size_t)k * 128 + g4 * 4);
        uint2 u; u.x = packh2(v.x, v.y); u.y = packh2(v.z, v.w);
        *(uint2*)(Ws + k * 272 + g4 * 8) = u;
    }
    __syncthreads();

    int g = lane >> 3, idx = lane & 7;
    float o[64];
#pragma unroll
    for (int i = 0; i < 64; i++) o[i] = 0.f;

#pragma unroll
    for (int kt = 0; kt < 8; kt++) {
        uint32_t a[4];
        int arow = w * 16 + (g & 1) * 8 + idx;
        ldsm_x4(a[0], a[1], a[2], a[3],
                cvta_s(Ns + arow * 272 + kt * 32 + (g >> 1) * 16));
#pragma unroll
        for (int nt2 = 0; nt2 < 8; nt2++) {
            int row = kt * 16 + (g & 1) * 8 + idx;
            uint32_t b0, b1, b2, b3;
            ldsm_x4_t(b0, b1, b2, b3,
                      cvta_s(Ws + row * 272 + nt2 * 32 + (g >> 1) * 16));
            mma_f16(o + (2 * nt2) * 4, a, b0, b1);
            mma_f16(o + (2 * nt2 + 1) * 4, a, b2, b3);
        }
    }

    if (m == 0) {
        float4 z = make_float4(0.f, 0.f, 0.f, 0.f);
        for (int i = tid; i < 2048; i += 128) {
            int r = i >> 5, g4 = i & 31;
            int gr = rbase + r;
            if (gr < NN) *(float4*)(g_aggB + (size_t)gr * 128 + g4 * 4) = z;
        }
    }

    int rr0 = w * 16 + (lane >> 2), rr1 = rr0 + 8;
    int gr0 = rbase + rr0, gr1 = rbase + rr1;
#pragma unroll
    for (int nt = 0; nt < 16; nt++) {
        int c = nt * 8 + 2 * (lane & 3);
        float v00 = (o[nt * 4 + 0] + cb_s[c]) * scale, v01 = (o[nt * 4 + 1] + cb_s[c + 1]) * scale;
        float v10 = (o[nt * 4 + 2] + cb_s[c]) * scale, v11 = (o[nt * 4 + 3] + cb_s[c + 1]) * scale;
        if (gr0 < NN) *(uint32_t*)((char*)out + (size_t)gr0 * 256 + c * 2) = packh2(v00, v01);
        if (gr1 < NN) *(uint32_t*)((char*)out + (size_t)gr1 * 256 + c * 2) = packh2(v10, v11);
    }
}

// ------------- split-KV flash attention: Br=128, Bc=128, TMA (SW128) K/V pipeline (R12 proven) -------------
// smem: Q [0, 34816) padded 272B rows | mbars [34816, 34832) | stages at 35840 (1024-aligned)
// stage layout: Kbox0 16KB | Kbox1 16KB | Vbox0 16KB | Vbox1 16KB = 64KB per stage
// K/V smem rows are 128B (64 fp16) SW128-swizzled: chunk16 ^= (row & 7)
#define KSTR 272
#define SM_MBAR 34816
#define SM_ST 35840
#define KV_STAGE 65536
#define SMEM_TOTAL (SM_ST + 2 * KV_STAGE)   // 166912

__global__ void __launch_bounds__(256, 1) attn_kernel(const __grid_constant__ CUtensorMap tmK,
                                                      const __grid_constant__ CUtensorMap tmV) {
    extern __shared__ char sm[];
    __half* Qs = (__half*)sm;
    int tid = threadIdx.x, lane = tid & 31, w = tid >> 5;
    int unit = blockIdx.x;
    int qtile = unit / NSPLIT, split = unit - qtile * NSPLIT;
    int rbase = qtile * 128;
    int kv0 = split * CHUNK;
    int kv1 = min(kv0 + CHUNK, NN);
    int niter = (kv1 - kv0 + 127) >> 7;   // 9 for all splits

    uint32_t smem_u32 = cvta_s(sm);
    uint32_t mb0 = smem_u32 + SM_MBAR;
    uint32_t mb1 = smem_u32 + SM_MBAR + 8;

    if (tid == 0) {
        mbar_init(mb0, 1);
        mbar_init(mb1, 1);
    }
    // Q tile: plain loads into padded 272B-row layout (one-time)
    for (int i = tid; i < 128 * 16; i += 256) {
        int r = i >> 4, ch = i & 15;
        int gr = min(rbase + r, NN - 1);
        *(uint4*)((char*)Qs + r * KSTR + ch * 16) =
            *(const uint4*)((const char*)g_Q + (size_t)gr * 256 + ch * 16);
    }
    __syncthreads();   // mbar init + Q visible

    // issue stage 0 and stage 1 K/V TMA loads (4 box ops each; OOB rows auto-zero)
    if (tid == 0) {
        mbar_expect(mb0, KV_STAGE);
        uint32_t st0 = smem_u32 + SM_ST;
        tma2d(st0 +     0, &tmK,  0, kv0, mb0);
        tma2d(st0 + 16384, &tmK, 64, kv0, mb0);
        tma2d(st0 + 32768, &tmV,  0, kv0, mb0);
        tma2d(st0 + 49152, &tmV, 64, kv0, mb0);
        mbar_expect(mb1, KV_STAGE);
        uint32_t st1 = smem_u32 + SM_ST + KV_STAGE;
        tma2d(st1 +     0, &tmK,  0, kv0 + 128, mb1);
        tma2d(st1 + 16384, &tmK, 64, kv0 + 128, mb1);
        tma2d(st1 + 32768, &tmV,  0, kv0 + 128, mb1);
        tma2d(st1 + 49152, &tmV, 64, kv0 + 128, mb1);
    }

    // preload Q a-frags
    uint32_t qa[8][4];
    {
        int g = lane >> 3, idx = lane & 7;
#pragma unroll
        for (int kt = 0; kt < 8; kt++) {
            int row = w * 16 + (g & 1) * 8 + idx;
            uint32_t a = cvta_s((char*)Qs + row * KSTR + kt * 32 + (g >> 1) * 16);
            ldsm_x4(qa[kt][0], qa[kt][1], qa[kt][2], qa[kt][3], a);
        }
    }

    float M0 = -1e30f, M1 = -1e30f, l0 = 0.f, l1 = 0.f;
    float o[64];
#pragma unroll
    for (int i = 0; i < 64; i++) o[i] = 0.f;

    for (int it = 0; it < niter; it++) {
        int jb = kv0 + it * 128;
        int st = it & 1;
        uint32_t stb = smem_u32 + SM_ST + st * KV_STAGE;
        uint32_t Kb = stb;             // K boxes
        uint32_t Vb = stb + 32768;     // V boxes
        uint32_t mb = st ? mb1 : mb0;

        mbar_wait(mb, (it >> 1) & 1);

        float s[64];
#pragma unroll
        for (int i = 0; i < 64; i++) s[i] = 0.f;

        // S = Q @ K^T  (K from SW128-swizzled 128B rows)
        {
            int g = lane >> 3, idx = lane & 7;
#pragma unroll
            for (int kt = 0; kt < 8; kt++) {
#pragma unroll
                for (int nt2 = 0; nt2 < 8; nt2++) {
                    int row = nt2 * 16 + (g & 2) * 4 + idx;
                    int chunk = ((kt * 2 + (g & 1)) & 7) ^ (row & 7);
                    uint32_t a = Kb + (kt >> 2) * 16384 + row * 128 + (chunk << 4);
                    uint32_t b0, b1, b2, b3;
                    ldsm_x4(b0, b1, b2, b3, a);
                    mma_f16(s + (2 * nt2) * 4, qa[kt], b0, b1);
                    mma_f16(s + (2 * nt2 + 1) * 4, qa[kt], b2, b3);
                }
            }
        }

        // mask tail keys
        if (jb + 128 > kv1) {
#pragma unroll
            for (int nt = 0; nt < 16; nt++) {
                int j0 = jb + nt * 8 + 2 * (lane & 3);
                if (j0 >= kv1) { s[nt * 4 + 0] = -1e30f; s[nt * 4 + 2] = -1e30f; }
                if (j0 + 1 >= kv1) { s[nt * 4 + 1] = -1e30f; s[nt * 4 + 3] = -1e30f; }
            }
        }

        // online softmax (exp2 domain) — R9 proven version
        float m0 = -1e30f, m1 = -1e30f;
#pragma unroll
        for (int nt = 0; nt < 16; nt++) {
            m0 = fmaxf(m0, fmaxf(s[nt * 4 + 0], s[nt * 4 + 1]));
            m1 = fmaxf(m1, fmaxf(s[nt * 4 + 2], s[nt * 4 + 3]));
        }
        m0 = fmaxf(m0, __shfl_xor_sync(0xffffffffu, m0, 1));
        m0 = fmaxf(m0, __shfl_xor_sync(0xffffffffu, m0, 2));
        m1 = fmaxf(m1, __shfl_xor_sync(0xffffffffu, m1, 1));
        m1 = fmaxf(m1, __shfl_xor_sync(0xffffffffu, m1, 2));
        float Mn0 = fmaxf(M0, m0), Mn1 = fmaxf(M1, m1);
        float sc0 = exp2f(M0 - Mn0), sc1 = exp2f(M1 - Mn1);
        M0 = Mn0; M1 = Mn1;
        float r0 = 0.f, r1 = 0.f;
#pragma unroll
        for (int nt = 0; nt < 16; nt++) {
            s[nt * 4 + 0] = exp2f(s[nt * 4 + 0] - M0);
            s[nt * 4 + 1] = exp2f(s[nt * 4 + 1] - M0);
            s[nt * 4 + 2] = exp2f(s[nt * 4 + 2] - M1);
            s[nt * 4 + 3] = exp2f(s[nt * 4 + 3] - M1);
            r0 += s[nt * 4 + 0] + s[nt * 4 + 1];
            r1 += s[nt * 4 + 2] + s[nt * 4 + 3];
        }
        r0 += __shfl_xor_sync(0xffffffffu, r0, 1);
        r0 += __shfl_xor_sync(0xffffffffu, r0, 2);
        r1 += __shfl_xor_sync(0xffffffffu, r1, 1);
        r1 += __shfl_xor_sync(0xffffffffu, r1, 2);
        l0 = l0 * sc0 + r0;
        l1 = l1 * sc1 + r1;
#pragma unroll
        for (int nt = 0; nt < 16; nt++) {
            o[nt * 4 + 0] *= sc0; o[nt * 4 + 1] *= sc0;
            o[nt * 4 + 2] *= sc1; o[nt * 4 + 3] *= sc1;
        }

        // O += P @ V  (V from SW128-swizzled 128B rows, trans ldsm)
        {
            int g = lane >> 3, idx = lane & 7;
#pragma unroll
            for (int kt = 0; kt < 8; kt++) {
                uint32_t pa[4];
                pa[0] = packh2(s[8 * kt + 0], s[8 * kt + 1]);
                pa[1] = packh2(s[8 * kt + 2], s[8 * kt + 3]);
                pa[2] = packh2(s[8 * kt + 4], s[8 * kt + 5]);
                pa[3] = packh2(s[8 * kt + 6], s[8 * kt + 7]);
#pragma unroll
                for (int nt2 = 0; nt2 < 8; nt2++) {
                    int row = kt * 16 + (g & 1) * 8 + idx;
                    int chunk = ((nt2 * 2 + (g >> 1)) & 7) ^ (row & 7);
                    uint32_t a = Vb + (nt2 >> 2) * 16384 + row * 128 + (chunk << 4);
                    uint32_t b0, b1, b2, b3;
                    ldsm_x4_t(b0, b1, b2, b3, a);
                    mma_f16(o + (2 * nt2) * 4, pa, b0, b1);
                    mma_f16(o + (2 * nt2 + 1) * 4, pa, b2, b3);
                }
            }
        }
        __syncthreads();   // all warps done reading stage st

        // refill this stage for iteration it+2
        if (it + 2 < niter && tid == 0) {
            int jn = kv0 + (it + 2) * 128;
            mbar_expect(mb, KV_STAGE);
            tma2d(stb +     0, &tmK,  0, jn, mb);
            tma2d(stb + 16384, &tmK, 64, jn, mb);
            tma2d(stb + 32768, &tmV,  0, jn, mb);
            tma2d(stb + 49152, &tmV, 64, jn, mb);
        }
    }

    // write partials (unnormalized o, plus m, l)
    int rr0 = w * 16 + (lane >> 2);
    int rr1 = rr0 + 8;
    size_t ubase = (size_t)unit * 128;
    if ((lane & 3) == 0) {
        g_pm[ubase + rr0] = M0;
        g_pl[ubase + rr0] = l0;
        g_pm[ubase + rr1] = M1;
        g_pl[ubase + rr1] = l1;
    }
#pragma unroll
    for (int nt = 0; nt < 16; nt++) {
        int c = nt * 8 + 2 * (lane & 3);
        *(float2*)&g_po[(ubase + rr0) * 128 + c] = make_float2(o[nt * 4 + 0], o[nt * 4 + 1]);
        *(float2*)&g_po[(ubase + rr1) * 128 + c] = make_float2(o[nt * 4 + 2], o[nt * 4 + 3]);
    }
}

// ------------- merge splits + column mean-sum -------------
__global__ void __launch_bounds__(128) merge_kernel() {
    int c = threadIdx.x;
    int rstart = blockIdx.x * 16;
    float acc = 0.f;
    for (int i = 0; i < 16; i++) {
        int r = rstart + i;
        if (r >= NN) break;
        int tile = r >> 7, row = r & 127;
        int base = tile * (NSPLIT * 128) + row;
        float M = -1e30f;
#pragma unroll
        for (int s = 0; s < NSPLIT; s++) M = fmaxf(M, g_pm[base + s * 128]);
        float L = 0.f, oc = 0.f;
#pragma unroll
        for (int s = 0; s < NSPLIT; s++) {
            float sc = exp2f(g_pm[base + s * 128] - M);
            L += g_pl[base + s * 128] * sc;
            oc += g_po[(size_t)(base + s * 128) * 128 + c] * sc;
        }
        acc += oc / L;
    }
    atomicAdd(&g_accum[c], acc);
}

// ------------- mean -> Wo -> MLP -> softmax; re-zeros g_accum -------------
__global__ void __launch_bounds__(128) final_kernel(const float* Wo, const float* bo,
                                                    const float* W1, const float* b1v,
                                                    const float* W2, const float* b2v,
                                                    const float* W3, const float* b3v,
                                                    float* out) {
    __shared__ float v0[128], v1[128], v2[64], v3[32], red[2];
    int t = threadIdx.x;
    v0[t] = g_accum[t] * (1.0f / NN);
    g_accum[t] = 0.f;   // replay invariant
    __syncthreads();
    float s = bo[t];
    for (int i = 0; i < 128; i++) s += v0[i] * Wo[i * 128 + t];
    v1[t] = s;
    __syncthreads();
    if (t < 64) {
        float s2 = b1v[t];
        for (int i = 0; i < 128; i++) s2 += v1[i] * W1[i * 64 + t];
        v2[t] = fmaxf(s2, 0.f);
    }
    __syncthreads();
    if (t < 32) {
        float s3 = b2v[t];
        for (int i = 0; i < 64; i++) s3 += v2[i] * W2[i * 32 + t];
        v3[t] = fmaxf(s3, 0.f);
    }
    __syncthreads();
    float lg = b3v[t];
    for (int i = 0; i < 32; i++) lg += v3[i] * W3[i * 128 + t];
    v1[t] = lg;
    __syncthreads();
    if (t == 0) {
        float mx = -1e30f;
        for (int i = 0; i < 128; i++) mx = fmaxf(mx, v1[i]);
        float sm = 0.f;
        for (int i = 0; i < 128; i++) sm += expf(v1[i] - mx);
        red[0] = mx; red[1] = sm;
    }
    __syncthreads();
    out[t] = expf(lg - red[0]) / red[1];
}

// ------------- launch -------------
extern "C" void kernel_launch(void* const* d_in, const int* in_sizes, int n_in,
                              void* d_out, int out_size) {
    const float* nf = (const float*)d_in[0];
    const float* gi = (const float*)d_in[1];
    const int* ei = (const int*)d_in[2];
    const float* W1_root = (const float*)d_in[3];
    const float* W1_rel = (const float*)d_in[4];
    const float* b1 = (const float*)d_in[5];
    const float* W2_root = (const float*)d_in[6];
    const float* W2_rel = (const float*)d_in[7];
    const float* b2 = (const float*)d_in[8];
    const float* WQ = (const float*)d_in[9];
    const float* bQ = (const float*)d_in[10];
    const float* WK = (const float*)d_in[11];
    const float* bK = (const float*)d_in[12];
    const float* WV = (const float*)d_in[13];
    const float* bV = (const float*)d_in[14];
    const float* WQg = (const float*)d_in[15];
    const float* bQg = (const float*)d_in[16];
    const float* WKg = (const float*)d_in[17];
    const float* bKg = (const float*)d_in[18];
    const float* WVg = (const float*)d_in[19];
    const float* bVg = (const float*)d_in[20];
    const float* Wo = (const float*)d_in[21];
    const float* bo = (const float*)d_in[22];
    const float* Wfc1 = (const float*)d_in[23];
    const float* bfc1 = (const float*)d_in[24];
    const float* Wfc2 = (const float*)d_in[25];
    const float* bfc2 = (const float*)d_in[26];
    const float* Wfc3 = (const float*)d_in[27];
    const float* bfc3 = (const float*)d_in[28];

    static int attr_set = 0;
    static CUtensorMap h_tmK, h_tmV;
    if (!attr_set) {
        cudaFuncSetAttribute(attn_kernel, cudaFuncAttributeMaxDynamicSharedMemorySize, SMEM_TOTAL);
        cudaFuncSetAttribute(convmma_kernel, cudaFuncAttributeMaxDynamicSharedMemorySize, CONV_SMEM);
        cudaFuncSetAttribute(qkvmma_kernel, cudaFuncAttributeMaxDynamicSharedMemorySize, QKV_SMEM);

        typedef CUresult (*PFN_encode)(CUtensorMap*, CUtensorMapDataType, cuuint32_t, void*,
                                       const cuuint64_t*, const cuuint64_t*,
                                       const cuuint32_t*, const cuuint32_t*,
                                       CUtensorMapInterleave, CUtensorMapSwizzle,
                                       CUtensorMapL2promotion, CUtensorMapFloatOOBfill);
        PFN_encode encode = nullptr;
        cudaDriverEntryPointQueryResult qr;
        cudaGetDriverEntryPoint("cuTensorMapEncodeTiled", (void**)&encode,
                                cudaEnableDefault, &qr);
        void *pK = nullptr, *pV = nullptr;
        cudaGetSymbolAddress(&pK, g_K);
        cudaGetSymbolAddress(&pV, g_V);
        cuuint64_t dims[2] = {128, NN};
        cuuint64_t strides[1] = {256};            // bytes between rows
        cuuint32_t box[2] = {64, 128};            // 64 fp16 = 128B (SW128 limit), 128 rows
        cuuint32_t estr[2] = {1, 1};
        encode(&h_tmK, CU_TENSOR_MAP_DATA_TYPE_FLOAT16, 2, pK, dims, strides, box, estr,
               CU_TENSOR_MAP_INTERLEAVE_NONE, CU_TENSOR_MAP_SWIZZLE_128B,
               CU_TENSOR_MAP_L2_PROMOTION_L2_128B, CU_TENSOR_MAP_FLOAT_OOB_FILL_NONE);
        encode(&h_tmV, CU_TENSOR_MAP_DATA_TYPE_FLOAT16, 2, pV, dims, strides, box, estr,
               CU_TENSOR_MAP_INTERLEAVE_NONE, CU_TENSOR_MAP_SWIZZLE_128B,
               CU_TENSOR_MAP_L2_PROMOTION_L2_128B, CU_TENSOR_MAP_FLOAT_OOB_FILL_NONE);
        attr_set = 1;
    }

    scatter_kernel<<<20000, 256>>>(nf, ei, 0);                                   // 0 -> aggA
    convmma_kernel<<<157, 256, CONV_SMEM>>>(nf, W1_root, W1_rel, b1, 0);         // 1 reads aggA
    scatter_kernel<<<20000, 256>>>(nf, ei, 1);                                   // 2 -> aggB
    convmma_kernel<<<157, 256, CONV_SMEM>>>(nf, W2_root, W2_rel, b2, 1);         // 3 reads aggB, zeros aggA  <- ncu slot
    qkvmma_kernel<<<dim3(157, 3), 128, QKV_SMEM>>>(gi, WQ, bQ, WQg, bQg,
                                                   WK, bK, WKg, bKg,
                                                   WV, bV, WVg, bVg);            // 4 zeros aggB (m==0)
    attn_kernel<<<NQT * NSPLIT, 256, SMEM_TOTAL>>>(h_tmK, h_tmV);                // 5
    merge_kernel<<<625, 128>>>();                                                // 6
    final_kernel<<<1, 128>>>(Wo, bo, Wfc1, bfc1, Wfc2, bfc2, Wfc3, bfc3, (float*)d_out);  // 7
}

// round 15
// speedup vs baseline: 1.2731x; 1.0527x over previous
#include <cuda_runtime.h>
#include <cuda.h>
#include <cuda_fp16.h>
#include <cstdint>

#define NN 10000
#define EE 160000
// log2(e)/sqrt(128) folded into Q so softmax runs in exp2 domain
#define QSCALE 0.12752532f

#define NSPLIT 9
#define CHUNK 1112
#define NQT 79          // ceil(10000/128) Q tiles

// ------------- device scratch (static, zero-initialized, no allocation) -------------
__device__ float g_aggA[NN * 128];       // scatter#1 target; zeroed by conv stage 1
__device__ float g_aggB[NN * 128];       // scatter#2 target; zeroed by qkv (m==0)
__device__ float g_h[NN * 128];          // conv0 out fp32 (scatter#2 input)
__device__ __half g_h16[NN * 128];       // conv0 out fp16 (conv1 A input)
__device__ __half g_ne16[NN * 128];      // conv1 out fp16 (qkv A input)
__device__ __half g_Q[NN * 128];
__device__ __half g_K[NN * 128];
__device__ __half g_V[NN * 128];
__device__ float g_accum[128];           // zeroed by final_kernel after read
__device__ float g_pm[NQT * NSPLIT * 128];
__device__ float g_pl[NQT * NSPLIT * 128];
__device__ __half g_po[(size_t)NQT * NSPLIT * 128 * 128];   // fp16 partials (halved traffic)

// ------------- helpers -------------
__device__ __forceinline__ uint32_t cvta_s(const void* p) {
    return (uint32_t)__cvta_generic_to_shared(p);
}
__device__ __forceinline__ void ldsm_x4(uint32_t& r0, uint32_t& r1, uint32_t& r2, uint32_t& r3, uint32_t a) {
    asm volatile("ldmatrix.sync.aligned.m8n8.x4.shared.b16 {%0,%1,%2,%3}, [%4];"
                 : "=r"(r0), "=r"(r1), "=r"(r2), "=r"(r3) : "r"(a));
}
__device__ __forceinline__ void ldsm_x4_t(uint32_t& r0, uint32_t& r1, uint32_t& r2, uint32_t& r3, uint32_t a) {
    asm volatile("ldmatrix.sync.aligned.m8n8.x4.trans.shared.b16 {%0,%1,%2,%3}, [%4];"
                 : "=r"(r0), "=r"(r1), "=r"(r2), "=r"(r3) : "r"(a));
}
__device__ __forceinline__ void mma_f16(float* c, const uint32_t* a, uint32_t b0, uint32_t b1) {
    asm volatile(
        "mma.sync.aligned.m16n8k16.row.col.f32.f16.f16.f32 "
        "{%0,%1,%2,%3},{%4,%5,%6,%7},{%8,%9},{%0,%1,%2,%3};\n"
        : "+f"(c[0]), "+f"(c[1]), "+f"(c[2]), "+f"(c[3])
        : "r"(a[0]), "r"(a[1]), "r"(a[2]), "r"(a[3]), "r"(b0), "r"(b1));
}
__device__ __forceinline__ uint32_t packh2(float lo, float hi) {
    __half2 h = __floats2half2_rn(lo, hi);
    return *reinterpret_cast<uint32_t*>(&h);
}
// ---- TMA + mbarrier (attention K/V pipeline; proven R12) ----
__device__ __forceinline__ void tma2d(uint32_t dst, const CUtensorMap* map,
                                      int x, int y, uint32_t mbar) {
    asm volatile("cp.async.bulk.tensor.2d.shared::cta.global.tile.mbarrier::complete_tx::bytes "
                 "[%0], [%1, {%2, %3}], [%4];"
                 :: "r"(dst), "l"(map), "r"(x), "r"(y), "r"(mbar) : "memory");
}
__device__ __forceinline__ void mbar_init(uint32_t mbar, uint32_t count) {
    asm volatile("mbarrier.init.shared.b64 [%0], %1;" :: "r"(mbar), "r"(count) : "memory");
}
__device__ __forceinline__ void mbar_expect(uint32_t mbar, uint32_t bytes) {
    asm volatile("mbarrier.arrive.expect_tx.shared.b64 _, [%0], %1;"
                 :: "r"(mbar), "r"(bytes) : "memory");
}
__device__ __forceinline__ void mbar_wait(uint32_t mbar, uint32_t parity) {
    asm volatile(
        "{\n\t"
        ".reg .pred P1;\n\t"
        "WAIT_LOOP_%=:\n\t"
        "mbarrier.try_wait.parity.acquire.cta.shared::cta.b64 P1, [%0], %1, 0x989680;\n\t"
        "@P1 bra.uni WAIT_DONE_%=;\n\t"
        "bra.uni WAIT_LOOP_%=;\n\t"
        "WAIT_DONE_%=:\n\t"
        "}"
        :: "r"(mbar), "r"(parity) : "memory");
}

// ------------- segment_sum(x[src], dst) -------------
__global__ void scatter_kernel(const float* __restrict__ xin, const int* __restrict__ ei, int useH) {
    const float* x = useH ? g_h : xin;
    float* agg = useH ? g_aggB : g_aggA;
    long idx = (long)blockIdx.x * 256 + threadIdx.x;
    int e = (int)(idx >> 5);
    if (e >= EE) return;
    int q = ((int)idx & 31) * 4;
    int s = ei[e];
    int d = ei[EE + e];
    float4 v = *(const float4*)(x + (size_t)s * 128 + q);
    float* dp = agg + (size_t)d * 128 + q;
    asm volatile("red.global.add.v4.f32 [%0], {%1,%2,%3,%4};"
                 :: "l"(dp), "f"(v.x), "f"(v.y), "f"(v.z), "f"(v.w) : "memory");
}

// ------------- GraphConv on tensor cores, 256 thr (R10 measured version) -------------
#define CONV_SMEM (17408 * 2 + 34816 * 2)
__global__ void __launch_bounds__(256) convmma_kernel(const float* __restrict__ Xin,
                                                      const float* __restrict__ Wr,
                                                      const float* __restrict__ Wl,
                                                      const float* __restrict__ bias,
                                                      int stage) {
    extern __shared__ char smc[];
    char* Xs  = smc;
    char* As2 = smc + 17408;
    char* Wrs = smc + 34816;
    char* Wls = smc + 69632;
    __shared__ float bias_s[128];
    int tid = threadIdx.x, lane = tid & 31, w = tid >> 5;
    int rbase = blockIdx.x * 64;
    if (tid < 128) bias_s[tid] = bias[tid];

    const float* AGG = stage ? g_aggB : g_aggA;

    if (stage == 0) {
        for (int i = tid; i < 2048; i += 256) {
            int r = i >> 5, g4 = i & 31;
            int gr = rbase + r;
            float4 v = (gr < NN) ? *(const float4*)(Xin + (size_t)gr * 128 + g4 * 4)
                                 : make_float4(0.f, 0.f, 0.f, 0.f);
            uint2 u;
            u.x = packh2(v.x, v.y);
            u.y = packh2(v.z, v.w);
            *(uint2*)(Xs + r * 272 + g4 * 8) = u;
        }
    } else {
        for (int i = tid; i < 1024; i += 256) {
            int r = i >> 4, ch = i & 15;
            int gr = min(rbase + r, NN - 1);
            *(uint4*)(Xs + r * 272 + ch * 16) =
                *(const uint4*)((const char*)g_h16 + (size_t)gr * 256 + ch * 16);
        }
    }
    for (int i = tid; i < 2048; i += 256) {
        int r = i >> 5, g4 = i & 31;
        int gr = rbase + r;
        float4 v = (gr < NN) ? *(const float4*)(AGG + (size_t)gr * 128 + g4 * 4)
                             : make_float4(0.f, 0.f, 0.f, 0.f);
        uint2 u;
        u.x = packh2(v.x, v.y);
        u.y = packh2(v.z, v.w);
        *(uint2*)(As2 + r * 272 + g4 * 8) = u;
    }
    for (int i = tid; i < 4096; i += 256) {
        int k = i >> 5, g4 = i & 31;
        float4 v = *(const float4*)(Wr + (size_t)k * 128 + g4 * 4);
        uint2 u; u.x = packh2(v.x, v.y); u.y = packh2(v.z, v.w);
        *(uint2*)(Wrs + k * 272 + g4 * 8) = u;
        float4 v2 = *(const float4*)(Wl + (size_t)k * 128 + g4 * 4);
        uint2 u2; u2.x = packh2(v2.x, v2.y); u2.y = packh2(v2.z, v2.w);
        *(uint2*)(Wls + k * 272 + g4 * 8) = u2;
    }
    __syncthreads();

    int g = lane >> 3, idx = lane & 7;
    int wr_ = w & 3;
    int wc_ = w >> 2;
    float o[32];
#pragma unroll
    for (int i = 0; i < 32; i++) o[i] = 0.f;

#pragma unroll
    for (int pass = 0; pass < 2; pass++) {
        char* Abuf = pass ? As2 : Xs;
        char* Wbuf = pass ? Wls : Wrs;
#pragma unroll
        for (int kt = 0; kt < 8; kt++) {
            uint32_t a[4];
            int arow = wr_ * 16 + (g & 1) * 8 + idx;
            ldsm_x4(a[0], a[1], a[2], a[3],
                    cvta_s(Abuf + arow * 272 + kt * 32 + (g >> 1) * 16));
#pragma unroll
            for (int nt2l = 0; nt2l < 4; nt2l++) {
                int nt2 = wc_ * 4 + nt2l;
                int row = kt * 16 + (g & 1) * 8 + idx;
                uint32_t b0, b1, b2, b3;
                ldsm_x4_t(b0, b1, b2, b3,
                          cvta_s(Wbuf + row * 272 + nt2 * 32 + (g >> 1) * 16));
                mma_f16(o + (2 * nt2l) * 4, a, b0, b1);
                mma_f16(o + (2 * nt2l + 1) * 4, a, b2, b3);
            }
        }
    }

    if (stage) {
        float4 z = make_float4(0.f, 0.f, 0.f, 0.f);
        for (int i = tid; i < 2048; i += 256) {
            int r = i >> 5, g4 = i & 31;
            int gr = rbase + r;
            if (gr < NN) *(float4*)(g_aggA + (size_t)gr * 128 + g4 * 4) = z;
        }
    }

    int rr0 = wr_ * 16 + (lane >> 2), rr1 = rr0 + 8;
    int gr0 = rbase + rr0, gr1 = rbase + rr1;
#pragma unroll
    for (int nt = 0; nt < 8; nt++) {
        int c = wc_ * 64 + nt * 8 + 2 * (lane & 3);
        float v00 = o[nt * 4 + 0] + bias_s[c], v01 = o[nt * 4 + 1] + bias_s[c + 1];
        float v10 = o[nt * 4 + 2] + bias_s[c], v11 = o[nt * 4 + 3] + bias_s[c + 1];
        if (stage == 0) {
            v00 = fmaxf(v00, 0.f); v01 = fmaxf(v01, 0.f);
            v10 = fmaxf(v10, 0.f); v11 = fmaxf(v11, 0.f);
            if (gr0 < NN) {
                *(float2*)(g_h + (size_t)gr0 * 128 + c) = make_float2(v00, v01);
                *(uint32_t*)((char*)g_h16 + (size_t)gr0 * 256 + c * 2) = packh2(v00, v01);
            }
            if (gr1 < NN) {
                *(float2*)(g_h + (size_t)gr1 * 128 + c) = make_float2(v10, v11);
                *(uint32_t*)((char*)g_h16 + (size_t)gr1 * 256 + c * 2) = packh2(v10, v11);
            }
        } else {
            if (gr0 < NN)
                *(uint32_t*)((char*)g_ne16 + (size_t)gr0 * 256 + c * 2) = packh2(v00, v01);
            if (gr1 < NN)
                *(uint32_t*)((char*)g_ne16 + (size_t)gr1 * 256 + c * 2) = packh2(v10, v11);
        }
    }
}

// ------------- QKV on tensor cores, 256 thr (conv-proven structure) -------------
// 8 warps: warp w = rows (w&3)*16.. x cols (w>>2)*64..; grid (157, 3)
#define QKV_SMEM (17408 + 34816)
__global__ void __launch_bounds__(256) qkvmma_kernel(const float* __restrict__ gi,
                                                     const float* __restrict__ WQ, const float* __restrict__ bQ,
                                                     const float* __restrict__ WQg, const float* __restrict__ bQg,
                                                     const float* __restrict__ WK, const float* __restrict__ bK,
                                                     const float* __restrict__ WKg, const float* __restrict__ bKg,
                                                     const float* __restrict__ WV, const float* __restrict__ bV,
                                                     const float* __restrict__ WVg, const float* __restrict__ bVg) {
    extern __shared__ char smq[];
    char* Ns = smq;
    char* Ws = smq + 17408;
    __shared__ float cb_s[128];
    int m = blockIdx.y;
    const float* W  = m == 0 ? WQ  : (m == 1 ? WK  : WV);
    const float* b  = m == 0 ? bQ  : (m == 1 ? bK  : bV);
    const float* bg = m == 0 ? bQg : (m == 1 ? bKg : bVg);
    const float* Wg = m == 0 ? WQg : (m == 1 ? WKg : WVg);
    __half* out = m == 0 ? g_Q : (m == 1 ? g_K : g_V);
    float scale = m == 0 ? QSCALE : 1.0f;
    int tid = threadIdx.x, lane = tid & 31, w = tid >> 5;
    int rbase = blockIdx.x * 64;

    if (tid < 128) {
        float s = b[tid] + bg[tid];
        for (int i = 0; i < 64; i++) s += gi[i] * Wg[i * 128 + tid];
        cb_s[tid] = s;
    }
    for (int i = tid; i < 1024; i += 256) {
        int r = i >> 4, ch = i & 15;
        int gr = min(rbase + r, NN - 1);
        *(uint4*)(Ns + r * 272 + ch * 16) =
            *(const uint4*)((const char*)g_ne16 + (size_t)gr * 256 + ch * 16);
    }
    for (int i = tid; i < 4096; i += 256) {
        int k = i >> 5, g4 = i & 31;
        float4 v = *(const float4*)(W + (size_t)k * 128 + g4 * 4);
        uint2 u; u.x = packh2(v.x, v.y); u.y = packh2(v.z, v.w);
        *(uint2*)(Ws + k * 272 + g4 * 8) = u;
    }
    __syncthreads();

    int g = lane >> 3, idx = lane & 7;
    int wr_ = w & 3;
    int wc_ = w >> 2;
    float o[32];
#pragma unroll
    for (int i = 0; i < 32; i++) o[i] = 0.f;

#pragma unroll
    for (int kt = 0; kt < 8; kt++) {
        uint32_t a[4];
        int arow = wr_ * 16 + (g & 1) * 8 + idx;
        ldsm_x4(a[0], a[1], a[2], a[3],
                cvta_s(Ns + arow * 272 + kt * 32 + (g >> 1) * 16));
#pragma unroll
        for (int nt2l = 0; nt2l < 4; nt2l++) {
            int nt2 = wc_ * 4 + nt2l;
            int row = kt * 16 + (g & 1) * 8 + idx;
            uint32_t b0, b1, b2, b3;
            ldsm_x4_t(b0, b1, b2, b3,
                      cvta_s(Ws + row * 272 + nt2 * 32 + (g >> 1) * 16));
            mma_f16(o + (2 * nt2l) * 4, a, b0, b1);
            mma_f16(o + (2 * nt2l + 1) * 4, a, b2, b3);
        }
    }

    // m==0: zero our g_aggB rows (replay invariant; race-free after conv stage 1)
    if (m == 0) {
        float4 z = make_float4(0.f, 0.f, 0.f, 0.f);
        for (int i = tid; i < 2048; i += 256) {
            int r = i >> 5, g4 = i & 31;
            int gr = rbase + r;
            if (gr < NN) *(float4*)(g_aggB + (size_t)gr * 128 + g4 * 4) = z;
        }
    }

    int rr0 = wr_ * 16 + (lane >> 2), rr1 = rr0 + 8;
    int gr0 = rbase + rr0, gr1 = rbase + rr1;
#pragma unroll
    for (int nt = 0; nt < 8; nt++) {
        int c = wc_ * 64 + nt * 8 + 2 * (lane & 3);
        float v00 = (o[nt * 4 + 0] + cb_s[c]) * scale, v01 = (o[nt * 4 + 1] + cb_s[c + 1]) * scale;
        float v10 = (o[nt * 4 + 2] + cb_s[c]) * scale, v11 = (o[nt * 4 + 3] + cb_s[c + 1]) * scale;
        if (gr0 < NN) *(uint32_t*)((char*)out + (size_t)gr0 * 256 + c * 2) = packh2(v00, v01);
        if (gr1 < NN) *(uint32_t*)((char*)out + (size_t)gr1 * 256 + c * 2) = packh2(v10, v11);
    }
}

// ------------- split-KV flash attention: Br=128, Bc=128, TMA (SW128) K/V pipeline (R12 proven) -------------
#define KSTR 272
#define SM_MBAR 34816
#define SM_ST 35840
#define KV_STAGE 65536
#define SMEM_TOTAL (SM_ST + 2 * KV_STAGE)   // 166912

__global__ void __launch_bounds__(256, 1) attn_kernel(const __grid_constant__ CUtensorMap tmK,
                                                      const __grid_constant__ CUtensorMap tmV) {
    extern __shared__ char sm[];
    __half* Qs = (__half*)sm;
    int tid = threadIdx.x, lane = tid & 31, w = tid >> 5;
    int unit = blockIdx.x;
    int qtile = unit / NSPLIT, split = unit - qtile * NSPLIT;
    int rbase = qtile * 128;
    int kv0 = split * CHUNK;
    int kv1 = min(kv0 + CHUNK, NN);
    int niter = (kv1 - kv0 + 127) >> 7;   // 9 for all splits

    uint32_t smem_u32 = cvta_s(sm);
    uint32_t mb0 = smem_u32 + SM_MBAR;
    uint32_t mb1 = smem_u32 + SM_MBAR + 8;

    if (tid == 0) {
        mbar_init(mb0, 1);
        mbar_init(mb1, 1);
    }
    // Q tile: plain loads into padded 272B-row layout (one-time)
    for (int i = tid; i < 128 * 16; i += 256) {
        int r = i >> 4, ch = i & 15;
        int gr = min(rbase + r, NN - 1);
        *(uint4*)((char*)Qs + r * KSTR + ch * 16) =
            *(const uint4*)((const char*)g_Q + (size_t)gr * 256 + ch * 16);
    }
    __syncthreads();   // mbar init + Q visible

    // issue stage 0 and stage 1 K/V TMA loads (4 box ops each; OOB rows auto-zero)
    if (tid == 0) {
        mbar_expect(mb0, KV_STAGE);
        uint32_t st0 = smem_u32 + SM_ST;
        tma2d(st0 +     0, &tmK,  0, kv0, mb0);
        tma2d(st0 + 16384, &tmK, 64, kv0, mb0);
        tma2d(st0 + 32768, &tmV,  0, kv0, mb0);
        tma2d(st0 + 49152, &tmV, 64, kv0, mb0);
        mbar_expect(mb1, KV_STAGE);
        uint32_t st1 = smem_u32 + SM_ST + KV_STAGE;
        tma2d(st1 +     0, &tmK,  0, kv0 + 128, mb1);
        tma2d(st1 + 16384, &tmK, 64, kv0 + 128, mb1);
        tma2d(st1 + 32768, &tmV,  0, kv0 + 128, mb1);
        tma2d(st1 + 49152, &tmV, 64, kv0 + 128, mb1);
    }

    // preload Q a-frags
    uint32_t qa[8][4];
    {
        int g = lane >> 3, idx = lane & 7;
#pragma unroll
        for (int kt = 0; kt < 8; kt++) {
            int row = w * 16 + (g & 1) * 8 + idx;
            uint32_t a = cvta_s((char*)Qs + row * KSTR + kt * 32 + (g >> 1) * 16);
            ldsm_x4(qa[kt][0], qa[kt][1], qa[kt][2], qa[kt][3], a);
        }
    }

    float M0 = -1e30f, M1 = -1e30f, l0 = 0.f, l1 = 0.f;
    float o[64];
#pragma unroll
    for (int i = 0; i < 64; i++) o[i] = 0.f;

    for (int it = 0; it < niter; it++) {
        int jb = kv0 + it * 128;
        int st = it & 1;
        uint32_t stb = smem_u32 + SM_ST + st * KV_STAGE;
        uint32_t Kb = stb;             // K boxes
        uint32_t Vb = stb + 32768;     // V boxes
        uint32_t mb = st ? mb1 : mb0;

        mbar_wait(mb, (it >> 1) & 1);

        float s[64];
#pragma unroll
        for (int i = 0; i < 64; i++) s[i] = 0.f;

        // S = Q @ K^T  (K from SW128-swizzled 128B rows)
        {
            int g = lane >> 3, idx = lane & 7;
#pragma unroll
            for (int kt = 0; kt < 8; kt++) {
#pragma unroll
                for (int nt2 = 0; nt2 < 8; nt2++) {
                    int row = nt2 * 16 + (g & 2) * 4 + idx;
                    int chunk = ((kt * 2 + (g & 1)) & 7) ^ (row & 7);
                    uint32_t a = Kb + (kt >> 2) * 16384 + row * 128 + (chunk << 4);
                    uint32_t b0, b1, b2, b3;
                    ldsm_x4(b0, b1, b2, b3, a);
                    mma_f16(s + (2 * nt2) * 4, qa[kt], b0, b1);
                    mma_f16(s + (2 * nt2 + 1) * 4, qa[kt], b2, b3);
                }
            }
        }

        // mask tail keys
        if (jb + 128 > kv1) {
#pragma unroll
            for (int nt = 0; nt < 16; nt++) {
                int j0 = jb + nt * 8 + 2 * (lane & 3);
                if (j0 >= kv1) { s[nt * 4 + 0] = -1e30f; s[nt * 4 + 2] = -1e30f; }
                if (j0 + 1 >= kv1) { s[nt * 4 + 1] = -1e30f; s[nt * 4 + 3] = -1e30f; }
            }
        }

        // online softmax (exp2 domain) — R9 proven version
        float m0 = -1e30f, m1 = -1e30f;
#pragma unroll
        for (int nt = 0; nt < 16; nt++) {
            m0 = fmaxf(m0, fmaxf(s[nt * 4 + 0], s[nt * 4 + 1]));
            m1 = fmaxf(m1, fmaxf(s[nt * 4 + 2], s[nt * 4 + 3]));
        }
        m0 = fmaxf(m0, __shfl_xor_sync(0xffffffffu, m0, 1));
        m0 = fmaxf(m0, __shfl_xor_sync(0xffffffffu, m0, 2));
        m1 = fmaxf(m1, __shfl_xor_sync(0xffffffffu, m1, 1));
        m1 = fmaxf(m1, __shfl_xor_sync(0xffffffffu, m1, 2));
        float Mn0 = fmaxf(M0, m0), Mn1 = fmaxf(M1, m1);
        float sc0 = exp2f(M0 - Mn0), sc1 = exp2f(M1 - Mn1);
        M0 = Mn0; M1 = Mn1;
        float r0 = 0.f, r1 = 0.f;
#pragma unroll
        for (int nt = 0; nt < 16; nt++) {
            s[nt * 4 + 0] = exp2f(s[nt * 4 + 0] - M0);
            s[nt * 4 + 1] = exp2f(s[nt * 4 + 1] - M0);
            s[nt * 4 + 2] = exp2f(s[nt * 4 + 2] - M1);
            s[nt * 4 + 3] = exp2f(s[nt * 4 + 3] - M1);
            r0 += s[nt * 4 + 0] + s[nt * 4 + 1];
            r1 += s[nt * 4 + 2] + s[nt * 4 + 3];
        }
        r0 += __shfl_xor_sync(0xffffffffu, r0, 1);
        r0 += __shfl_xor_sync(0xffffffffu, r0, 2);
        r1 += __shfl_xor_sync(0xffffffffu, r1, 1);
        r1 += __shfl_xor_sync(0xffffffffu, r1, 2);
        l0 = l0 * sc0 + r0;
        l1 = l1 * sc1 + r1;
#pragma unroll
        for (int nt = 0; nt < 16; nt++) {
            o[nt * 4 + 0] *= sc0; o[nt * 4 + 1] *= sc0;
            o[nt * 4 + 2] *= sc1; o[nt * 4 + 3] *= sc1;
        }

        // O += P @ V  (V from SW128-swizzled 128B rows, trans ldsm)
        {
            int g = lane >> 3, idx = lane & 7;
#pragma unroll
            for (int kt = 0; kt < 8; kt++) {
                uint32_t pa[4];
                pa[0] = packh2(s[8 * kt + 0], s[8 * kt + 1]);
                pa[1] = packh2(s[8 * kt + 2], s[8 * kt + 3]);
                pa[2] = packh2(s[8 * kt + 4], s[8 * kt + 5]);
                pa[3] = packh2(s[8 * kt + 6], s[8 * kt + 7]);
#pragma unroll
                for (int nt2 = 0; nt2 < 8; nt2++) {
                    int row = kt * 16 + (g & 1) * 8 + idx;
                    int chunk = ((nt2 * 2 + (g >> 1)) & 7) ^ (row & 7);
                    uint32_t a = Vb + (nt2 >> 2) * 16384 + row * 128 + (chunk << 4);
                    uint32_t b0, b1, b2, b3;
                    ldsm_x4_t(b0, b1, b2, b3, a);
                    mma_f16(o + (2 * nt2) * 4, pa, b0, b1);
                    mma_f16(o + (2 * nt2 + 1) * 4, pa, b2, b3);
                }
            }
        }
        __syncthreads();   // all warps done reading stage st

        // refill this stage for iteration it+2
        if (it + 2 < niter && tid == 0) {
            int jn = kv0 + (it + 2) * 128;
            mbar_expect(mb, KV_STAGE);
            tma2d(stb +     0, &tmK,  0, jn, mb);
            tma2d(stb + 16384, &tmK, 64, jn, mb);
            tma2d(stb + 32768, &tmV,  0, jn, mb);
            tma2d(stb + 49152, &tmV, 64, jn, mb);
        }
    }

    // write partials (unnormalized o as fp16 pairs, plus m, l)
    int rr0 = w * 16 + (lane >> 2);
    int rr1 = rr0 + 8;
    size_t ubase = (size_t)unit * 128;
    if ((lane & 3) == 0) {
        g_pm[ubase + rr0] = M0;
        g_pl[ubase + rr0] = l0;
        g_pm[ubase + rr1] = M1;
        g_pl[ubase + rr1] = l1;
    }
#pragma unroll
    for (int nt = 0; nt < 16; nt++) {
        int c = nt * 8 + 2 * (lane & 3);
        *(uint32_t*)&g_po[(ubase + rr0) * 128 + c] = packh2(o[nt * 4 + 0], o[nt * 4 + 1]);
        *(uint32_t*)&g_po[(ubase + rr1) * 128 + c] = packh2(o[nt * 4 + 2], o[nt * 4 + 3]);
    }
}

// ------------- merge splits (fp16 partials) + column mean-sum -------------
__global__ void __launch_bounds__(128) merge_kernel() {
    int c = threadIdx.x;
    int rstart = blockIdx.x * 16;
    float acc = 0.f;
    for (int i = 0; i < 16; i++) {
        int r = rstart + i;
        if (r >= NN) break;
        int tile = r >> 7, row = r & 127;
        int base = tile * (NSPLIT * 128) + row;
        float M = -1e30f;
#pragma unroll
        for (int s = 0; s < NSPLIT; s++) M = fmaxf(M, g_pm[base + s * 128]);
        float L = 0.f, oc = 0.f;
#pragma unroll
        for (int s = 0; s < NSPLIT; s++) {
            float sc = exp2f(g_pm[base + s * 128] - M);
            L += g_pl[base + s * 128] * sc;
            oc += __half2float(g_po[(size_t)(base + s * 128) * 128 + c]) * sc;
        }
        acc += oc / L;
    }
    atomicAdd(&g_accum[c], acc);
}

// ------------- mean -> Wo -> MLP -> softmax; re-zeros g_accum -------------
__global__ void __launch_bounds__(128) final_kernel(const float* Wo, const float* bo,
                                                    const float* W1, const float* b1v,
                                                    const float* W2, const float* b2v,
                                                    const float* W3, const float* b3v,
                                                    float* out) {
    __shared__ float v0[128], v1[128], v2[64], v3[32], red[2];
    int t = threadIdx.x;
    v0[t] = g_accum[t] * (1.0f / NN);
    g_accum[t] = 0.f;   // replay invariant
    __syncthreads();
    float s = bo[t];
    for (int i = 0; i < 128; i++) s += v0[i] * Wo[i * 128 + t];
    v1[t] = s;
    __syncthreads();
    if (t < 64) {
        float s2 = b1v[t];
        for (int i = 0; i < 128; i++) s2 += v1[i] * W1[i * 64 + t];
        v2[t] = fmaxf(s2, 0.f);
    }
    __syncthreads();
    if (t < 32) {
        float s3 = b2v[t];
        for (int i = 0; i < 64; i++) s3 += v2[i] * W2[i * 32 + t];
        v3[t] = fmaxf(s3, 0.f);
    }
    __syncthreads();
    float lg = b3v[t];
    for (int i = 0; i < 32; i++) lg += v3[i] * W3[i * 128 + t];
    v1[t] = lg;
    __syncthreads();
    if (t == 0) {
        float mx = -1e30f;
        for (int i = 0; i < 128; i++) mx = fmaxf(mx, v1[i]);
        float sm = 0.f;
        for (int i = 0; i < 128; i++) sm += expf(v1[i] - mx);
        red[0] = mx; red[1] = sm;
    }
    __syncthreads();
    out[t] = expf(lg - red[0]) / red[1];
}

// ------------- launch -------------
extern "C" void kernel_launch(void* const* d_in, const int* in_sizes, int n_in,
                              void* d_out, int out_size) {
    const float* nf = (const float*)d_in[0];
    const float* gi = (const float*)d_in[1];
    const int* ei = (const int*)d_in[2];
    const float* W1_root = (const float*)d_in[3];
    const float* W1_rel = (const float*)d_in[4];
    const float* b1 = (const float*)d_in[5];
    const float* W2_root = (const float*)d_in[6];
    const float* W2_rel = (const float*)d_in[7];
    const float* b2 = (const float*)d_in[8];
    const float* WQ = (const float*)d_in[9];
    const float* bQ = (const float*)d_in[10];
    const float* WK = (const float*)d_in[11];
    const float* bK = (const float*)d_in[12];
    const float* WV = (const float*)d_in[13];
    const float* bV = (const float*)d_in[14];
    const float* WQg = (const float*)d_in[15];
    const float* bQg = (const float*)d_in[16];
    const float* WKg = (const float*)d_in[17];
    const float* bKg = (const float*)d_in[18];
    const float* WVg = (const float*)d_in[19];
    const float* bVg = (const float*)d_in[20];
    const float* Wo = (const float*)d_in[21];
    const float* bo = (const float*)d_in[22];
    const float* Wfc1 = (const float*)d_in[23];
    const float* bfc1 = (const float*)d_in[24];
    const float* Wfc2 = (const float*)d_in[25];
    const float* bfc2 = (const float*)d_in[26];
    const float* Wfc3 = (const float*)d_in[27];
    const float* bfc3 = (const float*)d_in[28];

    static int attr_set = 0;
    static CUtensorMap h_tmK, h_tmV;
    if (!attr_set) {
        cudaFuncSetAttribute(attn_kernel, cudaFuncAttributeMaxDynamicSharedMemorySize, SMEM_TOTAL);
        cudaFuncSetAttribute(convmma_kernel, cudaFuncAttributeMaxDynamicSharedMemorySize, CONV_SMEM);
        cudaFuncSetAttribute(qkvmma_kernel, cudaFuncAttributeMaxDynamicSharedMemorySize, QKV_SMEM);

        typedef CUresult (*PFN_encode)(CUtensorMap*, CUtensorMapDataType, cuuint32_t, void*,
                                       const cuuint64_t*, const cuuint64_t*,
                                       const cuuint32_t*, const cuuint32_t*,
                                       CUtensorMapInterleave, CUtensorMapSwizzle,
                                       CUtensorMapL2promotion, CUtensorMapFloatOOBfill);
        PFN_encode encode = nullptr;
        cudaDriverEntryPointQueryResult qr;
        cudaGetDriverEntryPoint("cuTensorMapEncodeTiled", (void**)&encode,
                                cudaEnableDefault, &qr);
        void *pK = nullptr, *pV = nullptr;
        cudaGetSymbolAddress(&pK, g_K);
        cudaGetSymbolAddress(&pV, g_V);
        cuuint64_t dims[2] = {128, NN};
        cuuint64_t strides[1] = {256};            // bytes between rows
        cuuint32_t box[2] = {64, 128};            // 64 fp16 = 128B (SW128 limit), 128 rows
        cuuint32_t estr[2] = {1, 1};
        encode(&h_tmK, CU_TENSOR_MAP_DATA_TYPE_FLOAT16, 2, pK, dims, strides, box, estr,
               CU_TENSOR_MAP_INTERLEAVE_NONE, CU_TENSOR_MAP_SWIZZLE_128B,
               CU_TENSOR_MAP_L2_PROMOTION_L2_128B, CU_TENSOR_MAP_FLOAT_OOB_FILL_NONE);
        encode(&h_tmV, CU_TENSOR_MAP_DATA_TYPE_FLOAT16, 2, pV, dims, strides, box, estr,
               CU_TENSOR_MAP_INTERLEAVE_NONE, CU_TENSOR_MAP_SWIZZLE_128B,
               CU_TENSOR_MAP_L2_PROMOTION_L2_128B, CU_TENSOR_MAP_FLOAT_OOB_FILL_NONE);
        attr_set = 1;
    }

    scatter_kernel<<<20000, 256>>>(nf, ei, 0);                                   // 0 -> aggA
    convmma_kernel<<<157, 256, CONV_SMEM>>>(nf, W1_root, W1_rel, b1, 0);         // 1 reads aggA
    scatter_kernel<<<20000, 256>>>(nf, ei, 1);                                   // 2 -> aggB
    convmma_kernel<<<157, 256, CONV_SMEM>>>(nf, W2_root, W2_rel, b2, 1);         // 3 reads aggB, zeros aggA  <- ncu slot
    qkvmma_kernel<<<dim3(157, 3), 256, QKV_SMEM>>>(gi, WQ, bQ, WQg, bQg,
                                                   WK, bK, WKg, bKg,
                                                   WV, bV, WVg, bVg);            // 4 zeros aggB (m==0)
    attn_kernel<<<NQT * NSPLIT, 256, SMEM_TOTAL>>>(h_tmK, h_tmV);                // 5
    merge_kernel<<<625, 128>>>();                                                // 6
    final_kernel<<<1, 128>>>(Wo, bo, Wfc1, bfc1, Wfc2, bfc2, Wfc3, bfc3, (float*)d_out);  // 7
}